// round 2
// baseline (speedup 1.0000x reference)
#include <cuda_runtime.h>
#include <cstdint>

typedef unsigned long long ull;

// ---------- packed fp32x2 helpers (Blackwell FFMA2 — PTX-only path) ----------
__device__ __forceinline__ ull rep2(float a) {
    ull r; asm("mov.b64 %0, {%1, %1};" : "=l"(r) : "f"(a)); return r;
}
__device__ __forceinline__ void ffma2(ull& d, ull a, ull b) {
    asm("fma.rn.f32x2 %0, %1, %2, %0;" : "+l"(d) : "l"(a), "l"(b));
}
__device__ __forceinline__ float2 unpk(ull v) {
    float2 f; asm("mov.b64 {%0, %1}, %2;" : "=f"(f.x), "=f"(f.y) : "l"(v)); return f;
}

#define DPAD 304   // D=300 padded to multiple of 16; pad columns are ZERO

// scratch (no cudaMalloc allowed) : Wt[2][304][304], proj[2][16*512][304]
__device__ float g_Wt[2 * DPAD * DPAD];
__device__ float g_proj[2L * 16 * 512 * DPAD];

// ---------------- kernel 1: transpose + zero-pad W ----------------
__global__ void wt_kernel(const float* __restrict__ W2, const float* __restrict__ W3) {
    int idx = blockIdx.x * blockDim.x + threadIdx.x;
    if (idx >= 2 * DPAD * DPAD) return;
    int h = idx / (DPAD * DPAD);
    int rem = idx - h * DPAD * DPAD;
    int e = rem / DPAD, d = rem - e * DPAD;   // Wt[h][e][d] = W[d][e]
    const float* W = h ? W3 : W2;
    g_Wt[idx] = (e < 300 && d < 300) ? W[d * 300 + e] : 0.f;
}

// ---------------- kernel 2: proj = input2 @ W^T + b (both heads) ----------------
// GEMM M=8192 (b*w) x N=304 x K=300. CTA tile 64x64, 256 thr, 4x4 micro, f32x2.
__global__ __launch_bounds__(256) void proj_kernel(const float* __restrict__ in2,
                                                   const float* __restrict__ b2,
                                                   const float* __restrict__ b3) {
    __shared__ float As[16 * 65];   // [kk][r], stride 65 => conflict-free STS
    __shared__ float Bs[16 * 64];   // [kk][c]
    const int tid = threadIdx.x;
    const int tx = tid & 15, ty = tid >> 4;
    const int r0 = blockIdx.x * 64, c0 = blockIdx.y * 64;
    const int h = blockIdx.z;
    const float* Wt = g_Wt + h * DPAD * DPAD;
    const float* Arow = in2 + (size_t)r0 * 300;
    ull acc[8];
#pragma unroll
    for (int i = 0; i < 8; ++i) acc[i] = 0ULL;

    for (int kc = 0; kc < 19; ++kc) {
        const int k0 = kc * 16;
        __syncthreads();
        for (int i = tid; i < 1024; i += 256) {           // A tile (coalesced on k)
            int r = i >> 4, kk = i & 15, e = k0 + kk;
            As[kk * 65 + r] = (e < 300) ? Arow[r * 300 + e] : 0.f;
        }
        for (int i = tid; i < 1024; i += 256) {           // Wt tile (coalesced on c)
            int kk = i >> 6, c = i & 63, gc = c0 + c;
            Bs[kk * 64 + c] = (gc < DPAD) ? Wt[(k0 + kk) * DPAD + gc] : 0.f;
        }
        __syncthreads();
#pragma unroll
        for (int kk = 0; kk < 16; ++kk) {
            ull b01 = *(const ull*)&Bs[kk * 64 + 4 * tx];
            ull b23 = *(const ull*)&Bs[kk * 64 + 4 * tx + 2];
#pragma unroll
            for (int rr = 0; rr < 4; ++rr) {
                ull a = rep2(As[kk * 65 + 4 * ty + rr]);
                ffma2(acc[2 * rr], a, b01);
                ffma2(acc[2 * rr + 1], a, b23);
            }
        }
    }
    const float* bias = h ? b3 : b2;
    float* Pout = g_proj + (size_t)h * 8192 * DPAD;
#pragma unroll
    for (int rr = 0; rr < 4; ++rr) {
        int gr = r0 + 4 * ty + rr;
        float2 v01 = unpk(acc[2 * rr]);
        float2 v23 = unpk(acc[2 * rr + 1]);
        float v[4] = {v01.x, v01.y, v23.x, v23.y};
#pragma unroll
        for (int q = 0; q < 4; ++q) {
            int gc = c0 + 4 * tx + q;
            if (gc < DPAD)  // pad cols written as exact zero so fused K-loop needs no guard
                Pout[(size_t)gr * DPAD + gc] = (gc < 300) ? v[q] + bias[gc] : 0.f;
        }
    }
}

// ---------------- kernel 3: fused scores -> softmax -> out ----------------
// One CTA = (head h, batch b, 32 rows of T). 256 threads, 2 CTAs/SM.
// smem: S[32][516] (66,048 B) + union{ phase1 As[16][33]+Bs[16][128] | phase3 Cs[32][304] }
#define SDIM 516
#define SMEM_FLOATS (32 * SDIM + 32 * DPAD)

__global__ __launch_bounds__(256, 2) void attn_kernel(const float* __restrict__ in1,
                                                      const float* __restrict__ in2,
                                                      float* __restrict__ out) {
    extern __shared__ float sm[];
    float* S  = sm;                    // [32][516]
    float* As = sm + 32 * SDIM;        // [16][33]   phase 1
    float* Bs = As + 16 * 33;          // [16][128]  phase 1
    float* Cs = sm + 32 * SDIM;        // [32][304]  phase 3 (union)
    const int tid = threadIdx.x;
    const int b = blockIdx.y, h = blockIdx.z;
    const int t0 = blockIdx.x * 32;
    const float* A = in1 + ((size_t)b * 2048 + t0) * 300;
    const float* P = g_proj + ((size_t)h * 8192 + (size_t)b * 512) * DPAD;

    // ---- phase 1: S[t][w] = A[t,:] . proj[w,:]  (32x512x304, f32x2 4x4 micro) ----
    {
        const int tx = tid & 31, ty = tid >> 5;   // warp: single ty (A broadcast), tx covers 128 cols
        for (int wt = 0; wt < 4; ++wt) {
            const int w0 = wt * 128;
            ull acc[8];
#pragma unroll
            for (int i = 0; i < 8; ++i) acc[i] = 0ULL;
            for (int kc = 0; kc < 19; ++kc) {
                const int k0 = kc * 16;
                __syncthreads();
                for (int i = tid; i < 512; i += 256) {           // A chunk
                    int r = i >> 4, kk = i & 15, k = k0 + kk;
                    As[kk * 33 + r] = (k < 300) ? A[r * 300 + k] : 0.f;
                }
                for (int i = tid; i < 512; i += 256) {           // proj chunk (float4 on k)
                    int cw = i >> 2, kg = i & 3;
                    float4 v = *(const float4*)&P[(size_t)(w0 + cw) * DPAD + k0 + 4 * kg];
                    Bs[(4 * kg + 0) * 128 + cw] = v.x;
                    Bs[(4 * kg + 1) * 128 + cw] = v.y;
                    Bs[(4 * kg + 2) * 128 + cw] = v.z;
                    Bs[(4 * kg + 3) * 128 + cw] = v.w;
                }
                __syncthreads();
#pragma unroll
                for (int kk = 0; kk < 16; ++kk) {
                    ull b01 = *(const ull*)&Bs[kk * 128 + 4 * tx];
                    ull b23 = *(const ull*)&Bs[kk * 128 + 4 * tx + 2];
#pragma unroll
                    for (int rr = 0; rr < 4; ++rr) {
                        ull a = rep2(As[kk * 33 + 4 * ty + rr]);
                        ffma2(acc[2 * rr], a, b01);
                        ffma2(acc[2 * rr + 1], a, b23);
                    }
                }
            }
#pragma unroll
            for (int rr = 0; rr < 4; ++rr) {     // 8B-aligned packed stores, conflict-free
                *(ull*)&S[(4 * ty + rr) * SDIM + w0 + 4 * tx]     = acc[2 * rr];
                *(ull*)&S[(4 * ty + rr) * SDIM + w0 + 4 * tx + 2] = acc[2 * rr + 1];
            }
        }
    }
    __syncthreads();

    // ---- phase 2: softmax over w (512) ; warp handles 4 rows ----
    {
        const int warp = tid >> 5, lane = tid & 31;
#pragma unroll
        for (int rr = 0; rr < 4; ++rr) {
            float* Srow = S + (warp * 4 + rr) * SDIM;
            float m = -3.0e38f;
            for (int k = lane; k < 512; k += 32) m = fmaxf(m, Srow[k]);
#pragma unroll
            for (int off = 16; off; off >>= 1) m = fmaxf(m, __shfl_xor_sync(0xffffffffu, m, off));
            float s = 0.f;
            for (int k = lane; k < 512; k += 32) { float e = expf(Srow[k] - m); Srow[k] = e; s += e; }
#pragma unroll
            for (int off = 16; off; off >>= 1) s += __shfl_xor_sync(0xffffffffu, s, off);
            float inv = 1.f / s;
            for (int k = lane; k < 512; k += 32) Srow[k] *= inv;
        }
    }

    // ---- phase 3: out[t][d] = sum_w P[t][w] * attn[w][d]  (32x300x512) ----
    {
        const int row = tid >> 3, cg = tid & 7;   // thread: 1 row x (up to 10) float4 col groups
        const float* AT = in2 + (size_t)b * 512 * 300;
        ull acc[20];
#pragma unroll
        for (int i = 0; i < 20; ++i) acc[i] = 0ULL;
        for (int kc = 0; kc < 16; ++kc) {
            const int k0 = kc * 32;
            __syncthreads();   // kc=0: closes softmax; kc>0: protects Cs reuse
            for (int i = tid; i < 32 * DPAD; i += 256) {
                int wl = i / DPAD, c = i - wl * DPAD;
                Cs[i] = (c < 300) ? AT[(size_t)(k0 + wl) * 300 + c] : 0.f;
            }
            __syncthreads();
#pragma unroll 8
            for (int kk = 0; kk < 32; ++kk) {
                ull pp = rep2(S[row * SDIM + k0 + kk]);   // conflict-free: SDIM%32==4, 4 rows/warp
                const float* Ck = Cs + kk * DPAD;
#pragma unroll
                for (int j = 0; j < 10; ++j) {
                    int c = cg * 4 + 32 * j;
                    if (c < 300) {
                        ffma2(acc[2 * j],     pp, *(const ull*)&Ck[c]);
                        ffma2(acc[2 * j + 1], pp, *(const ull*)&Ck[c + 2]);
                    }
                }
            }
        }
        float* O = out + (((size_t)h * 16 + b) * 2048 + t0 + row) * 300;
#pragma unroll
        for (int j = 0; j < 10; ++j) {
            int c = cg * 4 + 32 * j;
            if (c < 300) {
                *(ull*)&O[c]     = acc[2 * j];
                *(ull*)&O[c + 2] = acc[2 * j + 1];
            }
        }
    }
}

// ---------------- launch ----------------
extern "C" void kernel_launch(void* const* d_in, const int* in_sizes, int n_in,
                              void* d_out, int out_size) {
    (void)in_sizes; (void)n_in; (void)out_size;
    const float* in1 = (const float*)d_in[0];
    const float* in2 = (const float*)d_in[1];
    const float* W2  = (const float*)d_in[2];
    const float* b2  = (const float*)d_in[3];
    const float* W3  = (const float*)d_in[4];
    const float* b3  = (const float*)d_in[5];
    float* out = (float*)d_out;

    wt_kernel<<<(2 * DPAD * DPAD + 255) / 256, 256>>>(W2, W3);
    proj_kernel<<<dim3(128, 5, 2), 256>>>(in2, b2, b3);

    size_t smem = SMEM_FLOATS * sizeof(float);   // 104,960 B -> 2 CTAs/SM
    cudaFuncSetAttribute(attn_kernel, cudaFuncAttributeMaxDynamicSharedMemorySize, (int)smem);
    attn_kernel<<<dim3(64, 16, 2), 256, smem>>>(in1, in2, out);
}

// round 3
// speedup vs baseline: 1.3998x; 1.3998x over previous
#include <cuda_runtime.h>
#include <cstdint>

typedef unsigned long long ull;
typedef unsigned int u32;

// ---------- packed fp32x2 helpers ----------
__device__ __forceinline__ ull rep2(float a) {
    ull r; asm("mov.b64 %0, {%1, %1};" : "=l"(r) : "f"(a)); return r;
}
__device__ __forceinline__ void ffma2(ull& d, ull a, ull b) {
    asm("fma.rn.f32x2 %0, %1, %2, %0;" : "+l"(d) : "l"(a), "l"(b));
}
__device__ __forceinline__ float2 unpk(ull v) {
    float2 f; asm("mov.b64 {%0, %1}, %2;" : "=f"(f.x), "=f"(f.y) : "l"(v)); return f;
}
// ---------- cp.async ----------
__device__ __forceinline__ void cpa16(u32 d, const void* s) {
    asm volatile("cp.async.cg.shared.global [%0], [%1], 16;" :: "r"(d), "l"(s));
}
__device__ __forceinline__ void cpa4(u32 d, const void* s) {
    asm volatile("cp.async.ca.shared.global [%0], [%1], 4;" :: "r"(d), "l"(s));
}
#define CP_COMMIT()   asm volatile("cp.async.commit_group;")
#define CP_WAIT_ALL() asm volatile("cp.async.wait_group 0;")

#define DPAD 304   // K padded to 304; pad rows/cols are ZERO

// scratch: Wt[2][304][304], projT[h][b][k=304][w=512] (K-major for phase-1 streaming)
__device__ float g_Wt[2 * DPAD * DPAD];
__device__ float g_projT[2L * 16 * DPAD * 512];

// ---------------- kernel 1: transpose + zero-pad W ----------------
__global__ void wt_kernel(const float* __restrict__ W2, const float* __restrict__ W3) {
    int idx = blockIdx.x * blockDim.x + threadIdx.x;
    if (idx >= 2 * DPAD * DPAD) return;
    int h = idx / (DPAD * DPAD);
    int rem = idx - h * DPAD * DPAD;
    int e = rem / DPAD, d = rem - e * DPAD;   // Wt[h][e][d] = W[d][e]
    const float* W = h ? W3 : W2;
    g_Wt[idx] = (e < 300 && d < 300) ? W[d * 300 + e] : 0.f;
}

// ---------------- kernel 2: projT[e][w] = (in2 @ W^T + b)^T ----------------
__global__ __launch_bounds__(256) void proj_kernel(const float* __restrict__ in2,
                                                   const float* __restrict__ b2,
                                                   const float* __restrict__ b3) {
    __shared__ float As[16 * 65];
    __shared__ float Bs[16 * 64];
    const int tid = threadIdx.x;
    const int tx = tid & 15, ty = tid >> 4;
    const int r0 = blockIdx.x * 64, c0 = blockIdx.y * 64;
    const int h = blockIdx.z;
    const float* Wt = g_Wt + h * DPAD * DPAD;
    const float* Arow = in2 + (size_t)r0 * 300;
    ull acc[8];
#pragma unroll
    for (int i = 0; i < 8; ++i) acc[i] = 0ULL;

    for (int kc = 0; kc < 19; ++kc) {
        const int k0 = kc * 16;
        __syncthreads();
        for (int i = tid; i < 1024; i += 256) {
            int r = i >> 4, kk = i & 15, e = k0 + kk;
            As[kk * 65 + r] = (e < 300) ? Arow[r * 300 + e] : 0.f;
        }
        for (int i = tid; i < 1024; i += 256) {
            int kk = i >> 6, c = i & 63, gc = c0 + c;
            Bs[kk * 64 + c] = (gc < DPAD) ? Wt[(k0 + kk) * DPAD + gc] : 0.f;
        }
        __syncthreads();
#pragma unroll
        for (int kk = 0; kk < 16; ++kk) {
            ull b01 = *(const ull*)&Bs[kk * 64 + 4 * tx];
            ull b23 = *(const ull*)&Bs[kk * 64 + 4 * tx + 2];
#pragma unroll
            for (int rr = 0; rr < 4; ++rr) {
                ull a = rep2(As[kk * 65 + 4 * ty + rr]);
                ffma2(acc[2 * rr], a, b01);
                ffma2(acc[2 * rr + 1], a, b23);
            }
        }
    }
    const float* bias = h ? b3 : b2;
#pragma unroll
    for (int rr = 0; rr < 4; ++rr) {
        int gr = r0 + 4 * ty + rr;             // global row = b*512 + w
        int bb = gr >> 9, w = gr & 511;
        float2 v01 = unpk(acc[2 * rr]);
        float2 v23 = unpk(acc[2 * rr + 1]);
        float v[4] = {v01.x, v01.y, v23.x, v23.y};
#pragma unroll
        for (int q = 0; q < 4; ++q) {
            int gc = c0 + 4 * tx + q;          // e (k of phase 1)
            if (gc < DPAD)                     // pad rows written as exact zero
                g_projT[(((size_t)h * 16 + bb) * DPAD + gc) * 512 + w] =
                    (gc < 300) ? v[q] + bias[gc] : 0.f;
        }
    }
}

// ---------------- kernel 3: fused scores -> softmax -> out ----------------
// CTA = (h, b, 32 t-rows), 256 threads, 2 CTAs/SM.
// smem: S[32][516] + union{ phase1: Bs[2][8][512] + As[2][8][33] | phase3: Cs[2][16][304] }
#define SDIM 516
#define SMEM_FLOATS (32 * SDIM + 9728)

__global__ __launch_bounds__(256, 2) void attn_kernel(const float* __restrict__ in1,
                                                      const float* __restrict__ in2,
                                                      float* __restrict__ out) {
    extern __shared__ float sm[];
    float* S = sm;                                  // [32][516]
    float* U = sm + 32 * SDIM;                      // union region (9728 floats)
    float* Bs[2] = {U, U + 4096};                   // phase1 [8][512] each
    float* Asb[2] = {U + 8192, U + 8192 + 264};     // phase1 [8][33] each
    float* Cs[2] = {U, U + 4864};                   // phase3 [16][304] each

    const int tid = threadIdx.x;
    const int b = blockIdx.y, h = blockIdx.z;
    const int t0 = blockIdx.x * 32;
    const float* A  = in1 + ((size_t)b * 2048 + t0) * 300;
    const float* Pt = g_projT + ((size_t)h * 16 + b) * DPAD * 512;   // [k][w]
    const float* AT = in2 + (size_t)b * 512 * 300;

    const int tx = tid & 31, ty = tid >> 5;         // warp = ty; rows 4ty..4ty+3

    // ================= phase 1: S = A . projT  (32 x 512, K=304) =================
    {
        // prefetch chunk 0
        {
            u32 bd = (u32)__cvta_generic_to_shared(Bs[0]);
            const float* src = Pt;                   // rows 0..7
#pragma unroll
            for (int i = 0; i < 4; ++i) cpa16(bd + (tid * 4 + i * 1024) * 4, src + tid * 4 + i * 1024);
            int kk = tid >> 5, r = tid & 31;
            cpa4((u32)__cvta_generic_to_shared(&Asb[0][kk * 33 + r]), A + r * 300 + kk);
            CP_COMMIT();
        }

        ull acc[32];
#pragma unroll
        for (int i = 0; i < 32; ++i) acc[i] = 0ULL;

        for (int kc = 0; kc < 38; ++kc) {
            const int cur = kc & 1;
            CP_WAIT_ALL();
            __syncthreads();                         // buf(cur) ready; buf(cur^1) free
            if (kc + 1 < 38) {
                const int k0n = (kc + 1) * 8;
                u32 bd = (u32)__cvta_generic_to_shared(Bs[cur ^ 1]);
                const float* src = Pt + (size_t)k0n * 512;
#pragma unroll
                for (int i = 0; i < 4; ++i) cpa16(bd + (tid * 4 + i * 1024) * 4, src + tid * 4 + i * 1024);
                int kk = tid >> 5, r = tid & 31, k = k0n + kk;
                if (k < 300) cpa4((u32)__cvta_generic_to_shared(&Asb[cur ^ 1][kk * 33 + r]), A + r * 300 + k);
                else Asb[cur ^ 1][kk * 33 + r] = 0.f;
                CP_COMMIT();
            }
            const float* Bc = Bs[cur];
            const float* Ac = Asb[cur];
#pragma unroll
            for (int kk = 0; kk < 8; ++kk) {
                ull bb[8];
#pragma unroll
                for (int q = 0; q < 8; ++q)          // stride-8B LDS.64: conflict-free
                    bb[q] = *(const ull*)&Bc[kk * 512 + 2 * tx + 64 * q];
#pragma unroll
                for (int rr = 0; rr < 4; ++rr) {
                    ull a = rep2(Ac[kk * 33 + 4 * ty + rr]);   // warp-broadcast
#pragma unroll
                    for (int q = 0; q < 8; ++q) ffma2(acc[rr * 8 + q], a, bb[q]);
                }
            }
        }
        // store S (same-warp rows)
#pragma unroll
        for (int rr = 0; rr < 4; ++rr)
#pragma unroll
            for (int q = 0; q < 8; ++q)
                *(ull*)&S[(4 * ty + rr) * SDIM + 2 * tx + 64 * q] = acc[rr * 8 + q];
    }
    __syncthreads();   // all phase-1 smem reads done (union region reused below)

    // ---- issue phase-3 chunk-0 prefetch; it overlaps the softmax ----
    {
        // zero pad cols (300..303) of both Cs buffers
        if (tid < 128) {
            int bf = tid >> 6, rw = (tid >> 2) & 15, c = 300 + (tid & 3);
            Cs[bf][rw * DPAD + c] = 0.f;
        }
        u32 cd = (u32)__cvta_generic_to_shared(Cs[0]);
        for (int i = tid; i < 1200; i += 256) {      // 16 rows x 75 float4
            int wl = i / 75, cq = i - wl * 75;
            cpa16(cd + (wl * DPAD + cq * 4) * 4, AT + (size_t)wl * 300 + cq * 4);
        }
        CP_COMMIT();
    }

    // ================= phase 2: softmax over w (rows are warp-local) =================
    {
        const int lane = tx;
#pragma unroll
        for (int rr = 0; rr < 4; ++rr) {
            float* Srow = S + (ty * 4 + rr) * SDIM;
            float m = -3.0e38f;
            for (int k = lane; k < 512; k += 32) m = fmaxf(m, Srow[k]);
#pragma unroll
            for (int off = 16; off; off >>= 1) m = fmaxf(m, __shfl_xor_sync(0xffffffffu, m, off));
            float s = 0.f;
            for (int k = lane; k < 512; k += 32) { float e = __expf(Srow[k] - m); Srow[k] = e; s += e; }
#pragma unroll
            for (int off = 16; off; off >>= 1) s += __shfl_xor_sync(0xffffffffu, s, off);
            float inv = 1.f / s;
            for (int k = lane; k < 512; k += 32) Srow[k] *= inv;
        }
    }

    // ================= phase 3: out = S . attn  (32 x 300, K=512) =================
    {
        const int row = tid >> 3, cg = tid & 7;
        ull acc[20];
#pragma unroll
        for (int i = 0; i < 20; ++i) acc[i] = 0ULL;

        for (int kc = 0; kc < 32; ++kc) {
            const int cur = kc & 1;
            CP_WAIT_ALL();
            __syncthreads();
            if (kc + 1 < 32) {
                const int k0n = (kc + 1) * 16;
                u32 cd = (u32)__cvta_generic_to_shared(Cs[cur ^ 1]);
                for (int i = tid; i < 1200; i += 256) {
                    int wl = i / 75, cq = i - wl * 75;
                    cpa16(cd + (wl * DPAD + cq * 4) * 4, AT + (size_t)(k0n + wl) * 300 + cq * 4);
                }
                CP_COMMIT();
            }
            const float* Cc = Cs[cur];
            const int k0 = kc * 16;
#pragma unroll
            for (int kk = 0; kk < 16; ++kk) {
                ull pp = rep2(S[row * SDIM + k0 + kk]);
                const float* Ck = Cc + kk * DPAD;
#pragma unroll
                for (int j = 0; j < 10; ++j) {
                    int c = cg * 4 + 32 * j;
                    if (c < 300) {
                        ffma2(acc[2 * j],     pp, *(const ull*)&Ck[c]);
                        ffma2(acc[2 * j + 1], pp, *(const ull*)&Ck[c + 2]);
                    }
                }
            }
        }
        float* O = out + (((size_t)h * 16 + b) * 2048 + t0 + row) * 300;
#pragma unroll
        for (int j = 0; j < 10; ++j) {
            int c = cg * 4 + 32 * j;
            if (c < 300) {
                *(ull*)&O[c]     = acc[2 * j];
                *(ull*)&O[c + 2] = acc[2 * j + 1];
            }
        }
    }
}

// ---------------- launch ----------------
extern "C" void kernel_launch(void* const* d_in, const int* in_sizes, int n_in,
                              void* d_out, int out_size) {
    (void)in_sizes; (void)n_in; (void)out_size;
    const float* in1 = (const float*)d_in[0];
    const float* in2 = (const float*)d_in[1];
    const float* W2  = (const float*)d_in[2];
    const float* b2  = (const float*)d_in[3];
    const float* W3  = (const float*)d_in[4];
    const float* b3  = (const float*)d_in[5];
    float* out = (float*)d_out;

    wt_kernel<<<(2 * DPAD * DPAD + 255) / 256, 256>>>(W2, W3);
    proj_kernel<<<dim3(128, 5, 2), 256>>>(in2, b2, b3);

    size_t smem = SMEM_FLOATS * sizeof(float);   // 104,960 B -> 2 CTAs/SM
    cudaFuncSetAttribute(attn_kernel, cudaFuncAttributeMaxDynamicSharedMemorySize, (int)smem);
    attn_kernel<<<dim3(64, 16, 2), 256, smem>>>(in1, in2, out);
}

// round 6
// speedup vs baseline: 3.8014x; 2.7157x over previous
#include <cuda_runtime.h>
#include <cuda_bf16.h>
#include <cstdint>

typedef unsigned long long ull;
typedef unsigned int u32;

// ---------- fp32x2 (proj kernel) ----------
__device__ __forceinline__ ull rep2(float a) { ull r; asm("mov.b64 %0, {%1, %1};" : "=l"(r) : "f"(a)); return r; }
__device__ __forceinline__ void ffma2(ull& d, ull a, ull b) { asm("fma.rn.f32x2 %0, %1, %2, %0;" : "+l"(d) : "l"(a), "l"(b)); }
__device__ __forceinline__ float2 unpk(ull v) { float2 f; asm("mov.b64 {%0, %1}, %2;" : "=f"(f.x), "=f"(f.y) : "l"(v)); return f; }
// ---------- cp.async ----------
__device__ __forceinline__ void cpa16(u32 d, const void* s) {
    asm volatile("cp.async.cg.shared.global [%0], [%1], 16;" :: "r"(d), "l"(s));
}
#define CP_COMMIT() asm volatile("cp.async.commit_group;")
// ---------- mma.sync / ldmatrix ----------
__device__ __forceinline__ u32 s2u(const void* p) { return (u32)__cvta_generic_to_shared(p); }
__device__ __forceinline__ void ldsm4(u32* r, u32 a) {
    asm volatile("ldmatrix.sync.aligned.m8n8.x4.shared.b16 {%0,%1,%2,%3}, [%4];"
                 : "=r"(r[0]), "=r"(r[1]), "=r"(r[2]), "=r"(r[3]) : "r"(a));
}
__device__ __forceinline__ void mma16816(float* c, const u32* a, u32 b0, u32 b1) {
    asm volatile("mma.sync.aligned.m16n8k16.row.col.f32.bf16.bf16.f32 "
                 "{%0,%1,%2,%3}, {%4,%5,%6,%7}, {%8,%9}, {%0,%1,%2,%3};"
                 : "+f"(c[0]), "+f"(c[1]), "+f"(c[2]), "+f"(c[3])
                 : "r"(a[0]), "r"(a[1]), "r"(a[2]), "r"(a[3]), "r"(b0), "r"(b1));
}
__device__ __forceinline__ u32 pk2(float up, float lo) {
    u32 d; asm("cvt.rn.bf16x2.f32 %0, %1, %2;" : "=r"(d) : "f"(up), "f"(lo)); return d;
}

#define KP 320
__device__ float g_Wt[2 * KP * KP];
__device__ float g_S[2L * 16 * 2048 * 512];
__device__ __nv_bfloat16 g_Ahi[16L * 2048 * KP], g_Alo[16L * 2048 * KP];
__device__ __nv_bfloat16 g_Whi[2L * 16 * 512 * KP], g_Wlo[2L * 16 * 512 * KP];
__device__ __nv_bfloat16 g_Vhi[16L * 384 * 512],  g_Vlo[16L * 384 * 512];
__device__ __nv_bfloat16 g_Phi[2L * 16 * 2048 * 512], g_Plo[2L * 16 * 2048 * 512];

// stage a 128-row x 64-col bf16 tile (128B rows) with XOR swizzle; 256 threads
__device__ __forceinline__ void ldt(u32 dst, const __nv_bfloat16* src, int pitch, int k0) {
    for (int i = threadIdx.x; i < 1024; i += 256) {
        int r = i >> 3, c = i & 7;
        cpa16(dst + r * 128 + ((c ^ (r & 7)) << 4), src + (size_t)r * pitch + k0 + c * 8);
    }
}

__global__ void split_in1(const float* __restrict__ in1) {
    size_t i = (size_t)blockIdx.x * 256 + threadIdx.x;
    if (i >= 16L * 2048 * KP) return;
    int k = (int)(i % KP); size_t bt = i / KP;
    float v = (k < 300) ? in1[bt * 300 + k] : 0.f;
    __nv_bfloat16 h = __float2bfloat16(v);
    g_Ahi[i] = h; g_Alo[i] = __float2bfloat16(v - __bfloat162float(h));
}

__global__ void wt_kernel(const float* __restrict__ W2, const float* __restrict__ W3) {
    int idx = blockIdx.x * blockDim.x + threadIdx.x;
    if (idx >= 2 * KP * KP) return;
    int h = idx / (KP * KP), rem = idx - h * (KP * KP);
    int e = rem / KP, d = rem - e * KP;
    const float* W = h ? W3 : W2;
    g_Wt[idx] = (e < 300 && d < 300) ? W[d * 300 + e] : 0.f;
}

__global__ void vt_kernel(const float* __restrict__ in2) {
    __shared__ float t[32][33];
    const int b = blockIdx.z, d0 = blockIdx.y * 32, w0 = blockIdx.x * 32;
    const int tx = threadIdx.x, ty = threadIdx.y;
    for (int yy = ty; yy < 32; yy += 8)
        t[yy][tx] = (d0 + tx < 300) ? in2[((size_t)b * 512 + w0 + yy) * 300 + d0 + tx] : 0.f;
    __syncthreads();
    for (int yy = ty; yy < 32; yy += 8) {
        float v = t[tx][yy];
        __nv_bfloat16 hi = __float2bfloat16(v);
        size_t o = ((size_t)b * 384 + d0 + yy) * 512 + w0 + tx;
        g_Vhi[o] = hi; g_Vlo[o] = __float2bfloat16(v - __bfloat162float(hi));
    }
}

// proj = in2 @ W^T + b  (exact fp32) -> W hi/lo bf16, [w][k] k-contiguous
__global__ __launch_bounds__(256) void proj_kernel(const float* __restrict__ in2,
                                                   const float* __restrict__ b2,
                                                   const float* __restrict__ b3) {
    __shared__ float As[16 * 65], Bs[16 * 64];
    const int tid = threadIdx.x, tx = tid & 15, ty = tid >> 4;
    const int r0 = blockIdx.x * 64, c0 = blockIdx.y * 64, h = blockIdx.z;
    const float* Wt = g_Wt + h * KP * KP;
    const float* Arow = in2 + (size_t)r0 * 300;
    ull acc[8];
#pragma unroll
    for (int i = 0; i < 8; ++i) acc[i] = 0ULL;
    for (int kc = 0; kc < 19; ++kc) {
        const int k0 = kc * 16;
        __syncthreads();
        for (int i = tid; i < 1024; i += 256) {
            int r = i >> 4, kk = i & 15, e = k0 + kk;
            As[kk * 65 + r] = (e < 300) ? Arow[r * 300 + e] : 0.f;
        }
        for (int i = tid; i < 1024; i += 256) {
            int kk = i >> 6, c = i & 63;
            Bs[kk * 64 + c] = Wt[(k0 + kk) * KP + c0 + c];
        }
        __syncthreads();
#pragma unroll
        for (int kk = 0; kk < 16; ++kk) {
            ull b01 = *(const ull*)&Bs[kk * 64 + 4 * tx];
            ull b23 = *(const ull*)&Bs[kk * 64 + 4 * tx + 2];
#pragma unroll
            for (int rr = 0; rr < 4; ++rr) {
                ull a = rep2(As[kk * 65 + 4 * ty + rr]);
                ffma2(acc[2 * rr], a, b01); ffma2(acc[2 * rr + 1], a, b23);
            }
        }
    }
    const float* bias = h ? b3 : b2;
#pragma unroll
    for (int rr = 0; rr < 4; ++rr) {
        int gr = r0 + 4 * ty + rr, bb = gr >> 9, w = gr & 511;
        float2 v01 = unpk(acc[2 * rr]), v23 = unpk(acc[2 * rr + 1]);
        float v[4] = {v01.x, v01.y, v23.x, v23.y};
#pragma unroll
        for (int q = 0; q < 4; ++q) {
            int gc = c0 + 4 * tx + q;
            float val = (gc < 300) ? v[q] + bias[gc] : 0.f;
            __nv_bfloat16 hi = __float2bfloat16(val);
            size_t o = (((size_t)h * 16 + bb) * 512 + w) * KP + gc;
            g_Whi[o] = hi; g_Wlo[o] = __float2bfloat16(val - __bfloat162float(hi));
        }
    }
}

// ================= mma.sync GEMM core (shared by scores/out) =================
// smem stage s: Ahi @ s*65536, Alo +16384, Bhi +32768, Blo +49152. 256 thr, warp=64x32.
template<int NCHUNK>
__device__ __forceinline__ void gemm3(u32 sb, const __nv_bfloat16* Ah, const __nv_bfloat16* Al,
                                      const __nv_bfloat16* Bh, const __nv_bfloat16* Bl,
                                      int pitch, float acc[4][4][4]) {
    const int lane = threadIdx.x & 31, wid = threadIdx.x >> 5;
    const int wm = wid >> 2, wn = wid & 3;
    ldt(sb,         Ah, pitch, 0); ldt(sb + 16384, Al, pitch, 0);
    ldt(sb + 32768, Bh, pitch, 0); ldt(sb + 49152, Bl, pitch, 0);
    CP_COMMIT();
    const int rA = wm * 64 + (lane & 15), rB = wn * 32 + (lane & 15);
    const int chalf = lane >> 4;
    for (int kc = 0; kc < NCHUNK; ++kc) {
        if (kc + 1 < NCHUNK) {
            u32 d = sb + ((kc + 1) & 1) * 65536;
            int k0 = (kc + 1) * 64;
            ldt(d, Ah, pitch, k0); ldt(d + 16384, Al, pitch, k0);
            ldt(d + 32768, Bh, pitch, k0); ldt(d + 49152, Bl, pitch, k0);
            CP_COMMIT();
            asm volatile("cp.async.wait_group 1;");
        } else {
            asm volatile("cp.async.wait_group 0;");
        }
        __syncthreads();
        u32 st = sb + (kc & 1) * 65536;
#pragma unroll
        for (int ks = 0; ks < 4; ++ks) {
            const int c16 = ks * 2 + chalf;
            const u32 offA = rA * 128 + (((u32)(c16 ^ (rA & 7))) << 4);
            const u32 offB = rB * 128 + (((u32)(c16 ^ (rB & 7))) << 4);
            u32 ah[4][4], al[4][4], bh[2][4], bl[2][4];
#pragma unroll
            for (int mi = 0; mi < 4; ++mi) {
                ldsm4(ah[mi], st + offA + mi * 2048);
                ldsm4(al[mi], st + 16384 + offA + mi * 2048);
            }
#pragma unroll
            for (int g = 0; g < 2; ++g) {
                ldsm4(bh[g], st + 32768 + offB + g * 2048);
                ldsm4(bl[g], st + 49152 + offB + g * 2048);
            }
#pragma unroll
            for (int mi = 0; mi < 4; ++mi)
#pragma unroll
                for (int g = 0; g < 2; ++g)
#pragma unroll
                    for (int sub = 0; sub < 2; ++sub) {
                        float* c = acc[mi][g * 2 + sub];
                        mma16816(c, ah[mi], bh[g][sub], bh[g][sub + 2]);
                        mma16816(c, ah[mi], bl[g][sub], bl[g][sub + 2]);
                        mma16816(c, al[mi], bh[g][sub], bh[g][sub + 2]);
                    }
        }
        __syncthreads();
    }
}

#define GEMM_SMEM 131072

// scores: S[t][w] fp32
__global__ __launch_bounds__(256) void scores_kernel() {
    extern __shared__ char sm[];
    const u32 sb = s2u(sm);
    const int lane = threadIdx.x & 31, wid = threadIdx.x >> 5;
    const int wm = wid >> 2, wn = wid & 3;
    const int t0 = blockIdx.x * 128, w0 = blockIdx.y * 128;
    const int b = blockIdx.z & 15, h = blockIdx.z >> 4, hb = h * 16 + b;
    float acc[4][4][4];
#pragma unroll
    for (int i = 0; i < 4; ++i)
#pragma unroll
        for (int j = 0; j < 4; ++j)
#pragma unroll
            for (int q = 0; q < 4; ++q) acc[i][j][q] = 0.f;
    gemm3<5>(sb,
             g_Ahi + ((size_t)b * 2048 + t0) * KP, g_Alo + ((size_t)b * 2048 + t0) * KP,
             g_Whi + ((size_t)hb * 512 + w0) * KP, g_Wlo + ((size_t)hb * 512 + w0) * KP,
             KP, acc);
    float* S = g_S + (size_t)hb * 2048 * 512;
#pragma unroll
    for (int mi = 0; mi < 4; ++mi)
#pragma unroll
        for (int ni = 0; ni < 4; ++ni) {
            int row = t0 + wm * 64 + mi * 16 + (lane >> 2);
            int col = w0 + wn * 32 + ni * 8 + 2 * (lane & 3);
            *(float2*)&S[(size_t)row * 512 + col]       = make_float2(acc[mi][ni][0], acc[mi][ni][1]);
            *(float2*)&S[(size_t)(row + 8) * 512 + col] = make_float2(acc[mi][ni][2], acc[mi][ni][3]);
        }
}

// softmax: warp per row -> P hi/lo bf16
__global__ __launch_bounds__(256) void softmax_kernel() {
    const int lane = threadIdx.x & 31;
    const size_t R = (size_t)blockIdx.x * 8 + (threadIdx.x >> 5);
    const float4* Srow = (const float4*)(g_S + R * 512);
    float v[16];
#pragma unroll
    for (int i = 0; i < 4; ++i) {
        float4 q = Srow[i * 32 + lane];
        v[4 * i] = q.x; v[4 * i + 1] = q.y; v[4 * i + 2] = q.z; v[4 * i + 3] = q.w;
    }
    float m = v[0];
#pragma unroll
    for (int i = 1; i < 16; ++i) m = fmaxf(m, v[i]);
#pragma unroll
    for (int o = 16; o; o >>= 1) m = fmaxf(m, __shfl_xor_sync(0xffffffffu, m, o));
    float s = 0.f;
#pragma unroll
    for (int i = 0; i < 16; ++i) { v[i] = __expf(v[i] - m); s += v[i]; }
#pragma unroll
    for (int o = 16; o; o >>= 1) s += __shfl_xor_sync(0xffffffffu, s, o);
    const float inv = 1.f / s;
    uint2* Ph = (uint2*)(g_Phi + R * 512);
    uint2* Pl = (uint2*)(g_Plo + R * 512);
#pragma unroll
    for (int i = 0; i < 4; ++i) {
        float e0 = v[4 * i] * inv, e1 = v[4 * i + 1] * inv, e2 = v[4 * i + 2] * inv, e3 = v[4 * i + 3] * inv;
        __nv_bfloat16 h0 = __float2bfloat16(e0), h1 = __float2bfloat16(e1);
        __nv_bfloat16 h2 = __float2bfloat16(e2), h3 = __float2bfloat16(e3);
        uint2 hv, lv;
        hv.x = ((u32)__bfloat16_as_ushort(h1) << 16) | __bfloat16_as_ushort(h0);
        hv.y = ((u32)__bfloat16_as_ushort(h3) << 16) | __bfloat16_as_ushort(h2);
        lv.x = pk2(e1 - __bfloat162float(h1), e0 - __bfloat162float(h0));
        lv.y = pk2(e3 - __bfloat162float(h3), e2 - __bfloat162float(h2));
        Ph[i * 32 + lane] = hv;
        Pl[i * 32 + lane] = lv;
    }
}

// out = P @ V : C[t][d]
__global__ __launch_bounds__(256) void out_kernel(float* __restrict__ out) {
    extern __shared__ char sm[];
    const u32 sb = s2u(sm);
    const int lane = threadIdx.x & 31, wid = threadIdx.x >> 5;
    const int wm = wid >> 2, wn = wid & 3;
    const int t0 = blockIdx.x * 128, d0 = blockIdx.y * 128;
    const int b = blockIdx.z & 15, h = blockIdx.z >> 4, hb = h * 16 + b;
    float acc[4][4][4];
#pragma unroll
    for (int i = 0; i < 4; ++i)
#pragma unroll
        for (int j = 0; j < 4; ++j)
#pragma unroll
            for (int q = 0; q < 4; ++q) acc[i][j][q] = 0.f;
    gemm3<8>(sb,
             g_Phi + ((size_t)hb * 2048 + t0) * 512, g_Plo + ((size_t)hb * 2048 + t0) * 512,
             g_Vhi + ((size_t)b * 384 + d0) * 512,  g_Vlo + ((size_t)b * 384 + d0) * 512,
             512, acc);
#pragma unroll
    for (int mi = 0; mi < 4; ++mi)
#pragma unroll
        for (int ni = 0; ni < 4; ++ni) {
            int row = t0 + wm * 64 + mi * 16 + (lane >> 2);
            int col = d0 + wn * 32 + ni * 8 + 2 * (lane & 3);
            if (col < 300) {
                *(float2*)&out[((size_t)hb * 2048 + row) * 300 + col] =
                    make_float2(acc[mi][ni][0], acc[mi][ni][1]);
                *(float2*)&out[((size_t)hb * 2048 + row + 8) * 300 + col] =
                    make_float2(acc[mi][ni][2], acc[mi][ni][3]);
            }
        }
}

extern "C" void kernel_launch(void* const* d_in, const int* in_sizes, int n_in,
                              void* d_out, int out_size) {
    (void)in_sizes; (void)n_in; (void)out_size;
    const float* in1 = (const float*)d_in[0];
    const float* in2 = (const float*)d_in[1];
    const float* W2  = (const float*)d_in[2];
    const float* b2  = (const float*)d_in[3];
    const float* W3  = (const float*)d_in[4];
    const float* b3  = (const float*)d_in[5];
    float* out = (float*)d_out;

    split_in1<<<(int)((16L * 2048 * KP + 255) / 256), 256>>>(in1);
    wt_kernel<<<(2 * KP * KP + 255) / 256, 256>>>(W2, W3);
    vt_kernel<<<dim3(16, 12, 16), dim3(32, 8)>>>(in2);
    proj_kernel<<<dim3(128, 5, 2), 256>>>(in2, b2, b3);

    cudaFuncSetAttribute(scores_kernel, cudaFuncAttributeMaxDynamicSharedMemorySize, GEMM_SMEM);
    scores_kernel<<<dim3(16, 4, 32), 256, GEMM_SMEM>>>();

    softmax_kernel<<<8192, 256>>>();

    cudaFuncSetAttribute(out_kernel, cudaFuncAttributeMaxDynamicSharedMemorySize, GEMM_SMEM);
    out_kernel<<<dim3(16, 3, 32), 256, GEMM_SMEM>>>(out);
}

// round 7
// speedup vs baseline: 4.1983x; 1.1044x over previous
#include <cuda_runtime.h>
#include <cuda_bf16.h>
#include <cstdint>

typedef unsigned long long ull;
typedef unsigned int u32;

// ---------- cp.async ----------
__device__ __forceinline__ void cpa16(u32 d, const void* s) {
    asm volatile("cp.async.cg.shared.global [%0], [%1], 16;" :: "r"(d), "l"(s));
}
#define CP_COMMIT() asm volatile("cp.async.commit_group;")
// ---------- mma.sync / ldmatrix ----------
__device__ __forceinline__ u32 s2u(const void* p) { return (u32)__cvta_generic_to_shared(p); }
__device__ __forceinline__ void ldsm4(u32* r, u32 a) {
    asm volatile("ldmatrix.sync.aligned.m8n8.x4.shared.b16 {%0,%1,%2,%3}, [%4];"
                 : "=r"(r[0]), "=r"(r[1]), "=r"(r[2]), "=r"(r[3]) : "r"(a));
}
__device__ __forceinline__ void mma16816(float* c, const u32* a, u32 b0, u32 b1) {
    asm volatile("mma.sync.aligned.m16n8k16.row.col.f32.bf16.bf16.f32 "
                 "{%0,%1,%2,%3}, {%4,%5,%6,%7}, {%8,%9}, {%0,%1,%2,%3};"
                 : "+f"(c[0]), "+f"(c[1]), "+f"(c[2]), "+f"(c[3])
                 : "r"(a[0]), "r"(a[1]), "r"(a[2]), "r"(a[3]), "r"(b0), "r"(b1));
}
__device__ __forceinline__ u32 pk2(float up, float lo) {
    u32 d; asm("cvt.rn.bf16x2.f32 %0, %1, %2;" : "=r"(d) : "f"(up), "f"(lo)); return d;
}

#define KP 320
__device__ float g_S[2L * 16 * 2048 * 512];
__device__ __nv_bfloat16 g_Ahi[16L * 2048 * KP], g_Alo[16L * 2048 * KP];
__device__ __nv_bfloat16 g_I2hi[16L * 512 * KP], g_I2lo[16L * 512 * KP];
__device__ __nv_bfloat16 g_Wsphi[2L * 384 * KP], g_Wsplo[2L * 384 * KP];   // pads: zero-init
__device__ __nv_bfloat16 g_Whi[2L * 16 * 512 * KP], g_Wlo[2L * 16 * 512 * KP]; // cols>=300: zero-init
__device__ __nv_bfloat16 g_Vhi[16L * 384 * 512],  g_Vlo[16L * 384 * 512];
__device__ __nv_bfloat16 g_Phi[2L * 16 * 2048 * 512], g_Plo[2L * 16 * 2048 * 512];

// stage 128-row x 64-col bf16 tile (128B rows), XOR swizzle; 256 threads
__device__ __forceinline__ void ldt(u32 dst, const __nv_bfloat16* src, int pitch, int k0) {
    for (int i = threadIdx.x; i < 1024; i += 256) {
        int r = i >> 3, c = i & 7;
        cpa16(dst + r * 128 + ((c ^ (r & 7)) << 4), src + (size_t)r * pitch + k0 + c * 8);
    }
}

__global__ void split_in1(const float* __restrict__ in1) {
    size_t i = (size_t)blockIdx.x * 256 + threadIdx.x;
    if (i >= 16L * 2048 * KP) return;
    int k = (int)(i % KP); size_t bt = i / KP;
    float v = (k < 300) ? in1[bt * 300 + k] : 0.f;
    __nv_bfloat16 h = __float2bfloat16(v);
    g_Ahi[i] = h; g_Alo[i] = __float2bfloat16(v - __bfloat162float(h));
}

__global__ void split_in2(const float* __restrict__ in2) {
    size_t i = (size_t)blockIdx.x * 256 + threadIdx.x;
    if (i >= 16L * 512 * KP) return;
    int k = (int)(i % KP); size_t bw = i / KP;
    float v = (k < 300) ? in2[bw * 300 + k] : 0.f;
    __nv_bfloat16 h = __float2bfloat16(v);
    g_I2hi[i] = h; g_I2lo[i] = __float2bfloat16(v - __bfloat162float(h));
}

__global__ void wsplit_kernel(const float* __restrict__ W2, const float* __restrict__ W3) {
    int idx = blockIdx.x * blockDim.x + threadIdx.x;
    if (idx >= 2 * 300 * 300) return;
    int h = idx / (300 * 300), rem = idx - h * 300 * 300;
    int e = rem / 300, d = rem - e * 300;
    float v = (h ? W3 : W2)[e * 300 + d];
    __nv_bfloat16 hi = __float2bfloat16(v);
    size_t o = ((size_t)h * 384 + e) * KP + d;
    g_Wsphi[o] = hi; g_Wsplo[o] = __float2bfloat16(v - __bfloat162float(hi));
}

__global__ void vt_kernel(const float* __restrict__ in2) {
    __shared__ float t[32][33];
    const int b = blockIdx.z, d0 = blockIdx.y * 32, w0 = blockIdx.x * 32;
    const int tx = threadIdx.x, ty = threadIdx.y;
    for (int yy = ty; yy < 32; yy += 8)
        t[yy][tx] = (d0 + tx < 300) ? in2[((size_t)b * 512 + w0 + yy) * 300 + d0 + tx] : 0.f;
    __syncthreads();
    for (int yy = ty; yy < 32; yy += 8) {
        float v = t[tx][yy];
        __nv_bfloat16 hi = __float2bfloat16(v);
        size_t o = ((size_t)b * 384 + d0 + yy) * 512 + w0 + tx;
        g_Vhi[o] = hi; g_Vlo[o] = __float2bfloat16(v - __bfloat162float(hi));
    }
}

// ========== mma.sync GEMM core, 3-stage cp.async pipeline ==========
// stage s at sb + s*65536: Ahi +0, Alo +16384, Bhi +32768, Blo +49152
template<int NCHUNK>
__device__ __forceinline__ void gemm3(u32 sb, const __nv_bfloat16* Ah, const __nv_bfloat16* Al,
                                      const __nv_bfloat16* Bh, const __nv_bfloat16* Bl,
                                      int pitch, float acc[4][4][4]) {
    const int lane = threadIdx.x & 31, wid = threadIdx.x >> 5;
    const int wm = wid >> 2, wn = wid & 3;
    ldt(sb,          Ah, pitch, 0);  ldt(sb + 16384,          Al, pitch, 0);
    ldt(sb + 32768,  Bh, pitch, 0);  ldt(sb + 49152,          Bl, pitch, 0);
    CP_COMMIT();
    ldt(sb + 65536,  Ah, pitch, 64); ldt(sb + 65536 + 16384,  Al, pitch, 64);
    ldt(sb + 65536 + 32768, Bh, pitch, 64); ldt(sb + 65536 + 49152, Bl, pitch, 64);
    CP_COMMIT();
    const int rA = wm * 64 + (lane & 15), rB = wn * 32 + (lane & 15);
    const int chalf = lane >> 4;
    for (int kc = 0; kc < NCHUNK; ++kc) {
        if (kc + 2 < NCHUNK) {
            u32 d = sb + ((kc + 2) % 3) * 65536;
            int k0 = (kc + 2) * 64;
            ldt(d, Ah, pitch, k0); ldt(d + 16384, Al, pitch, k0);
            ldt(d + 32768, Bh, pitch, k0); ldt(d + 49152, Bl, pitch, k0);
            CP_COMMIT();
            asm volatile("cp.async.wait_group 2;");
        } else if (kc + 1 < NCHUNK) {
            asm volatile("cp.async.wait_group 1;");
        } else {
            asm volatile("cp.async.wait_group 0;");
        }
        __syncthreads();
        u32 st = sb + (kc % 3) * 65536;
#pragma unroll
        for (int ks = 0; ks < 4; ++ks) {
            const int c16 = ks * 2 + chalf;
            const u32 offA = rA * 128 + (((u32)(c16 ^ (rA & 7))) << 4);
            const u32 offB = rB * 128 + (((u32)(c16 ^ (rB & 7))) << 4);
            u32 ah[4][4], al[4][4], bh[2][4], bl[2][4];
#pragma unroll
            for (int mi = 0; mi < 4; ++mi) {
                ldsm4(ah[mi], st + offA + mi * 2048);
                ldsm4(al[mi], st + 16384 + offA + mi * 2048);
            }
#pragma unroll
            for (int g = 0; g < 2; ++g) {
                ldsm4(bh[g], st + 32768 + offB + g * 2048);
                ldsm4(bl[g], st + 49152 + offB + g * 2048);
            }
#pragma unroll
            for (int mi = 0; mi < 4; ++mi)
#pragma unroll
                for (int g = 0; g < 2; ++g)
#pragma unroll
                    for (int sub = 0; sub < 2; ++sub) {
                        float* c = acc[mi][g * 2 + sub];
                        mma16816(c, ah[mi], bh[g][sub], bh[g][sub + 2]);
                        mma16816(c, ah[mi], bl[g][sub], bl[g][sub + 2]);
                        mma16816(c, al[mi], bh[g][sub], bh[g][sub + 2]);
                    }
        }
        __syncthreads();
    }
}

#define GEMM_SMEM 196608
#define ACC_ZERO(acc) do { _Pragma("unroll") for (int _i = 0; _i < 4; ++_i) \
    _Pragma("unroll") for (int _j = 0; _j < 4; ++_j) \
    _Pragma("unroll") for (int _q = 0; _q < 4; ++_q) acc[_i][_j][_q] = 0.f; } while (0)

// proj = in2 @ W^T + b  -> g_Whi/g_Wlo (scores B layout, [h*8192 + b*512 + w][e])
__global__ __launch_bounds__(256) void proj_mma(const float* __restrict__ b2,
                                                const float* __restrict__ b3) {
    extern __shared__ char sm[];
    const u32 sb = s2u(sm);
    const int lane = threadIdx.x & 31, wid = threadIdx.x >> 5;
    const int wm = wid >> 2, wn = wid & 3;
    const int t0 = blockIdx.x * 128, n0 = blockIdx.y * 128, h = blockIdx.z;
    float acc[4][4][4]; ACC_ZERO(acc);
    gemm3<5>(sb, g_I2hi + (size_t)t0 * KP, g_I2lo + (size_t)t0 * KP,
             g_Wsphi + ((size_t)h * 384 + n0) * KP, g_Wsplo + ((size_t)h * 384 + n0) * KP,
             KP, acc);
    const float* bias = h ? b3 : b2;
    __nv_bfloat16* Whi = g_Whi + (size_t)h * 8192 * KP;
    __nv_bfloat16* Wlo = g_Wlo + (size_t)h * 8192 * KP;
#pragma unroll
    for (int mi = 0; mi < 4; ++mi)
#pragma unroll
        for (int ni = 0; ni < 4; ++ni) {
            int row = t0 + wm * 64 + mi * 16 + (lane >> 2);
            int col = n0 + wn * 32 + ni * 8 + 2 * (lane & 3);
            if (col < 300) {
                float bc0 = bias[col], bc1 = bias[col + 1];
#pragma unroll
                for (int half = 0; half < 2; ++half) {
                    int r = row + half * 8;
                    float v0 = acc[mi][ni][2 * half] + bc0;
                    float v1 = acc[mi][ni][2 * half + 1] + bc1;
                    __nv_bfloat16 h0 = __float2bfloat16(v0), h1 = __float2bfloat16(v1);
                    u32 hp = ((u32)__bfloat16_as_ushort(h1) << 16) | __bfloat16_as_ushort(h0);
                    u32 lp = pk2(v1 - __bfloat162float(h1), v0 - __bfloat162float(h0));
                    *(u32*)&Whi[(size_t)r * KP + col] = hp;
                    *(u32*)&Wlo[(size_t)r * KP + col] = lp;
                }
            }
        }
}

// scores: S[t][w] fp32
__global__ __launch_bounds__(256) void scores_kernel() {
    extern __shared__ char sm[];
    const u32 sb = s2u(sm);
    const int lane = threadIdx.x & 31, wid = threadIdx.x >> 5;
    const int wm = wid >> 2, wn = wid & 3;
    const int t0 = blockIdx.x * 128, w0 = blockIdx.y * 128;
    const int b = blockIdx.z & 15, h = blockIdx.z >> 4, hb = h * 16 + b;
    float acc[4][4][4]; ACC_ZERO(acc);
    gemm3<5>(sb,
             g_Ahi + ((size_t)b * 2048 + t0) * KP, g_Alo + ((size_t)b * 2048 + t0) * KP,
             g_Whi + ((size_t)hb * 512 + w0) * KP, g_Wlo + ((size_t)hb * 512 + w0) * KP,
             KP, acc);
    float* S = g_S + (size_t)hb * 2048 * 512;
#pragma unroll
    for (int mi = 0; mi < 4; ++mi)
#pragma unroll
        for (int ni = 0; ni < 4; ++ni) {
            int row = t0 + wm * 64 + mi * 16 + (lane >> 2);
            int col = w0 + wn * 32 + ni * 8 + 2 * (lane & 3);
            *(float2*)&S[(size_t)row * 512 + col]       = make_float2(acc[mi][ni][0], acc[mi][ni][1]);
            *(float2*)&S[(size_t)(row + 8) * 512 + col] = make_float2(acc[mi][ni][2], acc[mi][ni][3]);
        }
}

// softmax: warp per row -> P hi/lo bf16
__global__ __launch_bounds__(256) void softmax_kernel() {
    const int lane = threadIdx.x & 31;
    const size_t R = (size_t)blockIdx.x * 8 + (threadIdx.x >> 5);
    const float4* Srow = (const float4*)(g_S + R * 512);
    float v[16];
#pragma unroll
    for (int i = 0; i < 4; ++i) {
        float4 q = Srow[i * 32 + lane];
        v[4 * i] = q.x; v[4 * i + 1] = q.y; v[4 * i + 2] = q.z; v[4 * i + 3] = q.w;
    }
    float m = v[0];
#pragma unroll
    for (int i = 1; i < 16; ++i) m = fmaxf(m, v[i]);
#pragma unroll
    for (int o = 16; o; o >>= 1) m = fmaxf(m, __shfl_xor_sync(0xffffffffu, m, o));
    float s = 0.f;
#pragma unroll
    for (int i = 0; i < 16; ++i) { v[i] = __expf(v[i] - m); s += v[i]; }
#pragma unroll
    for (int o = 16; o; o >>= 1) s += __shfl_xor_sync(0xffffffffu, s, o);
    const float inv = 1.f / s;
    uint2* Ph = (uint2*)(g_Phi + R * 512);
    uint2* Pl = (uint2*)(g_Plo + R * 512);
#pragma unroll
    for (int i = 0; i < 4; ++i) {
        float e0 = v[4 * i] * inv, e1 = v[4 * i + 1] * inv, e2 = v[4 * i + 2] * inv, e3 = v[4 * i + 3] * inv;
        __nv_bfloat16 h0 = __float2bfloat16(e0), h1 = __float2bfloat16(e1);
        __nv_bfloat16 h2 = __float2bfloat16(e2), h3 = __float2bfloat16(e3);
        uint2 hv, lv;
        hv.x = ((u32)__bfloat16_as_ushort(h1) << 16) | __bfloat16_as_ushort(h0);
        hv.y = ((u32)__bfloat16_as_ushort(h3) << 16) | __bfloat16_as_ushort(h2);
        lv.x = pk2(e1 - __bfloat162float(h1), e0 - __bfloat162float(h0));
        lv.y = pk2(e3 - __bfloat162float(h3), e2 - __bfloat162float(h2));
        Ph[i * 32 + lane] = hv;
        Pl[i * 32 + lane] = lv;
    }
}

// out = P @ V
__global__ __launch_bounds__(256) void out_kernel(float* __restrict__ out) {
    extern __shared__ char sm[];
    const u32 sb = s2u(sm);
    const int lane = threadIdx.x & 31, wid = threadIdx.x >> 5;
    const int wm = wid >> 2, wn = wid & 3;
    const int t0 = blockIdx.x * 128, d0 = blockIdx.y * 128;
    const int b = blockIdx.z & 15, h = blockIdx.z >> 4, hb = h * 16 + b;
    float acc[4][4][4]; ACC_ZERO(acc);
    gemm3<8>(sb,
             g_Phi + ((size_t)hb * 2048 + t0) * 512, g_Plo + ((size_t)hb * 2048 + t0) * 512,
             g_Vhi + ((size_t)b * 384 + d0) * 512,  g_Vlo + ((size_t)b * 384 + d0) * 512,
             512, acc);
#pragma unroll
    for (int mi = 0; mi < 4; ++mi)
#pragma unroll
        for (int ni = 0; ni < 4; ++ni) {
            int row = t0 + wm * 64 + mi * 16 + (lane >> 2);
            int col = d0 + wn * 32 + ni * 8 + 2 * (lane & 3);
            if (col < 300) {
                *(float2*)&out[((size_t)hb * 2048 + row) * 300 + col] =
                    make_float2(acc[mi][ni][0], acc[mi][ni][1]);
                *(float2*)&out[((size_t)hb * 2048 + row + 8) * 300 + col] =
                    make_float2(acc[mi][ni][2], acc[mi][ni][3]);
            }
        }
}

extern "C" void kernel_launch(void* const* d_in, const int* in_sizes, int n_in,
                              void* d_out, int out_size) {
    (void)in_sizes; (void)n_in; (void)out_size;
    const float* in1 = (const float*)d_in[0];
    const float* in2 = (const float*)d_in[1];
    const float* W2  = (const float*)d_in[2];
    const float* b2  = (const float*)d_in[3];
    const float* W3  = (const float*)d_in[4];
    const float* b3  = (const float*)d_in[5];
    float* out = (float*)d_out;

    split_in1<<<(int)((16L * 2048 * KP + 255) / 256), 256>>>(in1);
    split_in2<<<(int)((16L * 512 * KP + 255) / 256), 256>>>(in2);
    wsplit_kernel<<<(2 * 300 * 300 + 255) / 256, 256>>>(W2, W3);
    vt_kernel<<<dim3(16, 12, 16), dim3(32, 8)>>>(in2);

    cudaFuncSetAttribute(proj_mma, cudaFuncAttributeMaxDynamicSharedMemorySize, GEMM_SMEM);
    proj_mma<<<dim3(64, 3, 2), 256, GEMM_SMEM>>>(b2, b3);

    cudaFuncSetAttribute(scores_kernel, cudaFuncAttributeMaxDynamicSharedMemorySize, GEMM_SMEM);
    scores_kernel<<<dim3(16, 4, 32), 256, GEMM_SMEM>>>();

    softmax_kernel<<<8192, 256>>>();

    cudaFuncSetAttribute(out_kernel, cudaFuncAttributeMaxDynamicSharedMemorySize, GEMM_SMEM);
    out_kernel<<<dim3(16, 3, 32), 256, GEMM_SMEM>>>(out);
}

// round 8
// speedup vs baseline: 4.6092x; 1.0979x over previous
#include <cuda_runtime.h>
#include <cuda_bf16.h>
#include <cstdint>

typedef unsigned long long ull;
typedef unsigned int u32;
typedef __nv_bfloat16 bf16;

// ---------- cp.async ----------
__device__ __forceinline__ void cpa16(u32 d, const void* s) {
    asm volatile("cp.async.cg.shared.global [%0], [%1], 16;" :: "r"(d), "l"(s));
}
#define CP_COMMIT() asm volatile("cp.async.commit_group;")
// ---------- mma.sync / ldmatrix ----------
__device__ __forceinline__ u32 s2u(const void* p) { return (u32)__cvta_generic_to_shared(p); }
__device__ __forceinline__ void ldsm4(u32* r, u32 a) {
    asm volatile("ldmatrix.sync.aligned.m8n8.x4.shared.b16 {%0,%1,%2,%3}, [%4];"
                 : "=r"(r[0]), "=r"(r[1]), "=r"(r[2]), "=r"(r[3]) : "r"(a));
}
__device__ __forceinline__ void mma16816(float* c, const u32* a, u32 b0, u32 b1) {
    asm volatile("mma.sync.aligned.m16n8k16.row.col.f32.bf16.bf16.f32 "
                 "{%0,%1,%2,%3}, {%4,%5,%6,%7}, {%8,%9}, {%0,%1,%2,%3};"
                 : "+f"(c[0]), "+f"(c[1]), "+f"(c[2]), "+f"(c[3])
                 : "r"(a[0]), "r"(a[1]), "r"(a[2]), "r"(a[3]), "r"(b0), "r"(b1));
}
__device__ __forceinline__ u32 pk2(float up, float lo) {
    u32 d; asm("cvt.rn.bf16x2.f32 %0, %1, %2;" : "=r"(d) : "f"(up), "f"(lo)); return d;
}

#define KP 320
__device__ float g_S[2L * 16 * 2048 * 512];
__device__ bf16 g_Ahi[16L * 2048 * KP], g_Alo[16L * 2048 * KP];
__device__ bf16 g_I2hi[16L * 512 * KP], g_I2lo[16L * 512 * KP];
__device__ bf16 g_Wsphi[2L * 384 * KP], g_Wsplo[2L * 384 * KP];       // pads zero-init
__device__ bf16 g_Whi[2L * 16 * 512 * KP], g_Wlo[2L * 16 * 512 * KP]; // cols>=300 zero-init
__device__ bf16 g_Vhi[16L * 384 * 512],  g_Vlo[16L * 384 * 512];
__device__ bf16 g_Phi[2L * 16 * 2048 * 512], g_Plo[2L * 16 * 2048 * 512];

// stage rows x 64-col bf16 tile (128B rows), XOR swizzle; 256 threads
__device__ __forceinline__ void ldt(u32 dst, const bf16* src, int pitch, int k0, int rows) {
    for (int i = threadIdx.x; i < rows * 8; i += 256) {
        int r = i >> 3, c = i & 7;
        cpa16(dst + r * 128 + ((c ^ (r & 7)) << 4), src + (size_t)r * pitch + k0 + c * 8);
    }
}

__global__ void split_in1(const float* __restrict__ in1) {
    size_t i = (size_t)blockIdx.x * 256 + threadIdx.x;
    if (i >= 16L * 2048 * KP) return;
    int k = (int)(i % KP); size_t bt = i / KP;
    float v = (k < 300) ? in1[bt * 300 + k] : 0.f;
    bf16 h = __float2bfloat16(v);
    g_Ahi[i] = h; g_Alo[i] = __float2bfloat16(v - __bfloat162float(h));
}

__global__ void split_in2(const float* __restrict__ in2) {
    size_t i = (size_t)blockIdx.x * 256 + threadIdx.x;
    if (i >= 16L * 512 * KP) return;
    int k = (int)(i % KP); size_t bw = i / KP;
    float v = (k < 300) ? in2[bw * 300 + k] : 0.f;
    bf16 h = __float2bfloat16(v);
    g_I2hi[i] = h; g_I2lo[i] = __float2bfloat16(v - __bfloat162float(h));
}

__global__ void wsplit_kernel(const float* __restrict__ W2, const float* __restrict__ W3) {
    int idx = blockIdx.x * blockDim.x + threadIdx.x;
    if (idx >= 2 * 300 * 300) return;
    int h = idx / (300 * 300), rem = idx - h * 300 * 300;
    int e = rem / 300, d = rem - e * 300;
    float v = (h ? W3 : W2)[e * 300 + d];
    bf16 hi = __float2bfloat16(v);
    size_t o = ((size_t)h * 384 + e) * KP + d;
    g_Wsphi[o] = hi; g_Wsplo[o] = __float2bfloat16(v - __bfloat162float(hi));
}

__global__ void vt_kernel(const float* __restrict__ in2) {
    __shared__ float t[32][33];
    const int b = blockIdx.z, d0 = blockIdx.y * 32, w0 = blockIdx.x * 32;
    const int tx = threadIdx.x, ty = threadIdx.y;
    for (int yy = ty; yy < 32; yy += 8)
        t[yy][tx] = (d0 + tx < 300) ? in2[((size_t)b * 512 + w0 + yy) * 300 + d0 + tx] : 0.f;
    __syncthreads();
    for (int yy = ty; yy < 32; yy += 8) {
        float v = t[tx][yy];
        bf16 hi = __float2bfloat16(v);
        size_t o = ((size_t)b * 384 + d0 + yy) * 512 + w0 + tx;
        g_Vhi[o] = hi; g_Vlo[o] = __float2bfloat16(v - __bfloat162float(hi));
    }
}

// ========== mma.sync GEMM core: CTA 128 x (64*GN), warp 64 x (16*GN), 2-stage ==========
template<int NCHUNK, int GN>
__device__ __forceinline__ void gemm3(u32 sb, const bf16* Ah, const bf16* Al,
                                      const bf16* Bh, const bf16* Bl,
                                      int pitch, float acc[4][2 * GN][4]) {
    constexpr int BN = 64 * GN;
    constexpr u32 ASZ = 128 * 128;          // 16 KB per A half
    constexpr u32 BSZ = (u32)BN * 128;
    constexpr u32 STAGE = 2 * ASZ + 2 * BSZ;
    const int lane = threadIdx.x & 31, wid = threadIdx.x >> 5;
    const int wm = wid >> 2, wn = wid & 3;
    ldt(sb, Ah, pitch, 0, 128);             ldt(sb + ASZ, Al, pitch, 0, 128);
    ldt(sb + 2 * ASZ, Bh, pitch, 0, BN);    ldt(sb + 2 * ASZ + BSZ, Bl, pitch, 0, BN);
    CP_COMMIT();
    const int rA = wm * 64 + (lane & 15), rB = wn * (GN * 16) + (lane & 15);
    const int chalf = lane >> 4;
    for (int kc = 0; kc < NCHUNK; ++kc) {
        if (kc + 1 < NCHUNK) {
            u32 d = sb + ((kc + 1) & 1) * STAGE;
            int k0 = (kc + 1) * 64;
            ldt(d, Ah, pitch, k0, 128);          ldt(d + ASZ, Al, pitch, k0, 128);
            ldt(d + 2 * ASZ, Bh, pitch, k0, BN); ldt(d + 2 * ASZ + BSZ, Bl, pitch, k0, BN);
            CP_COMMIT();
            asm volatile("cp.async.wait_group 1;");
        } else {
            asm volatile("cp.async.wait_group 0;");
        }
        __syncthreads();
        u32 st = sb + (kc & 1) * STAGE;
#pragma unroll
        for (int ks = 0; ks < 4; ++ks) {
            const int c16 = ks * 2 + chalf;
            const u32 offA = rA * 128 + (((u32)(c16 ^ (rA & 7))) << 4);
            const u32 offB = rB * 128 + (((u32)(c16 ^ (rB & 7))) << 4);
            u32 ah[4][4], al[4][4], bh[GN][4], bl[GN][4];
#pragma unroll
            for (int mi = 0; mi < 4; ++mi) {
                ldsm4(ah[mi], st + offA + mi * 2048);
                ldsm4(al[mi], st + ASZ + offA + mi * 2048);
            }
#pragma unroll
            for (int g = 0; g < GN; ++g) {
                ldsm4(bh[g], st + 2 * ASZ + offB + g * 2048);
                ldsm4(bl[g], st + 2 * ASZ + BSZ + offB + g * 2048);
            }
#pragma unroll
            for (int mi = 0; mi < 4; ++mi)
#pragma unroll
                for (int g = 0; g < GN; ++g)
#pragma unroll
                    for (int sub = 0; sub < 2; ++sub) {
                        float* c = acc[mi][g * 2 + sub];
                        mma16816(c, ah[mi], bh[g][sub], bh[g][sub + 2]);
                        mma16816(c, ah[mi], bl[g][sub], bl[g][sub + 2]);
                        mma16816(c, al[mi], bh[g][sub], bh[g][sub + 2]);
                    }
        }
        __syncthreads();
    }
}

#define SMEM_GN4 196608
#define SMEM_GN2 131072
#define SMEM_GN1 98304
#define ACC_ZERO(acc, GN) do { _Pragma("unroll") for (int _i = 0; _i < 4; ++_i) \
    _Pragma("unroll") for (int _j = 0; _j < 2 * (GN); ++_j) \
    _Pragma("unroll") for (int _q = 0; _q < 4; ++_q) acc[_i][_j][_q] = 0.f; } while (0)

// proj = in2 @ W^T + b -> g_Whi/g_Wlo ([h*8192 + b*512 + w][e])
__global__ __launch_bounds__(256) void proj_mma(const float* __restrict__ b2,
                                                const float* __restrict__ b3) {
    extern __shared__ char sm[];
    const u32 sb = s2u(sm);
    const int lane = threadIdx.x & 31, wid = threadIdx.x >> 5;
    const int wm = wid >> 2, wn = wid & 3;
    const int t0 = blockIdx.x * 128, n0 = blockIdx.y * 128, h = blockIdx.z;
    float acc[4][4][4]; ACC_ZERO(acc, 2);
    gemm3<5, 2>(sb, g_I2hi + (size_t)t0 * KP, g_I2lo + (size_t)t0 * KP,
                g_Wsphi + ((size_t)h * 384 + n0) * KP, g_Wsplo + ((size_t)h * 384 + n0) * KP,
                KP, acc);
    const float* bias = h ? b3 : b2;
    bf16* Whi = g_Whi + (size_t)h * 8192 * KP;
    bf16* Wlo = g_Wlo + (size_t)h * 8192 * KP;
#pragma unroll
    for (int mi = 0; mi < 4; ++mi)
#pragma unroll
        for (int ni = 0; ni < 4; ++ni) {
            int row = t0 + wm * 64 + mi * 16 + (lane >> 2);
            int col = n0 + wn * 32 + ni * 8 + 2 * (lane & 3);
            if (col < 300) {
                float bc0 = bias[col], bc1 = bias[col + 1];
#pragma unroll
                for (int half = 0; half < 2; ++half) {
                    int r = row + half * 8;
                    float v0 = acc[mi][ni][2 * half] + bc0;
                    float v1 = acc[mi][ni][2 * half + 1] + bc1;
                    bf16 h0 = __float2bfloat16(v0), h1 = __float2bfloat16(v1);
                    u32 hp = ((u32)__bfloat16_as_ushort(h1) << 16) | __bfloat16_as_ushort(h0);
                    u32 lp = pk2(v1 - __bfloat162float(h1), v0 - __bfloat162float(h0));
                    *(u32*)&Whi[(size_t)r * KP + col] = hp;
                    *(u32*)&Wlo[(size_t)r * KP + col] = lp;
                }
            }
        }
}

// scores: S[t][w] fp32, CTA 128x256
__global__ __launch_bounds__(256) void scores_kernel() {
    extern __shared__ char sm[];
    const u32 sb = s2u(sm);
    const int lane = threadIdx.x & 31, wid = threadIdx.x >> 5;
    const int wm = wid >> 2, wn = wid & 3;
    const int t0 = blockIdx.x * 128, w0 = blockIdx.y * 256;
    const int b = blockIdx.z & 15, h = blockIdx.z >> 4, hb = h * 16 + b;
    float acc[4][8][4]; ACC_ZERO(acc, 4);
    gemm3<5, 4>(sb,
                g_Ahi + ((size_t)b * 2048 + t0) * KP, g_Alo + ((size_t)b * 2048 + t0) * KP,
                g_Whi + ((size_t)hb * 512 + w0) * KP, g_Wlo + ((size_t)hb * 512 + w0) * KP,
                KP, acc);
    float* S = g_S + (size_t)hb * 2048 * 512;
#pragma unroll
    for (int mi = 0; mi < 4; ++mi)
#pragma unroll
        for (int ni = 0; ni < 8; ++ni) {
            int row = t0 + wm * 64 + mi * 16 + (lane >> 2);
            int col = w0 + wn * 64 + ni * 8 + 2 * (lane & 3);
            *(float2*)&S[(size_t)row * 512 + col]       = make_float2(acc[mi][ni][0], acc[mi][ni][1]);
            *(float2*)&S[(size_t)(row + 8) * 512 + col] = make_float2(acc[mi][ni][2], acc[mi][ni][3]);
        }
}

// softmax: warp per row -> P hi/lo bf16
__global__ __launch_bounds__(256) void softmax_kernel() {
    const int lane = threadIdx.x & 31;
    const size_t R = (size_t)blockIdx.x * 8 + (threadIdx.x >> 5);
    const float4* Srow = (const float4*)(g_S + R * 512);
    float v[16];
#pragma unroll
    for (int i = 0; i < 4; ++i) {
        float4 q = Srow[i * 32 + lane];
        v[4 * i] = q.x; v[4 * i + 1] = q.y; v[4 * i + 2] = q.z; v[4 * i + 3] = q.w;
    }
    float m = v[0];
#pragma unroll
    for (int i = 1; i < 16; ++i) m = fmaxf(m, v[i]);
#pragma unroll
    for (int o = 16; o; o >>= 1) m = fmaxf(m, __shfl_xor_sync(0xffffffffu, m, o));
    float s = 0.f;
#pragma unroll
    for (int i = 0; i < 16; ++i) { v[i] = __expf(v[i] - m); s += v[i]; }
#pragma unroll
    for (int o = 16; o; o >>= 1) s += __shfl_xor_sync(0xffffffffu, s, o);
    const float inv = 1.f / s;
    uint2* Ph = (uint2*)(g_Phi + R * 512);
    uint2* Pl = (uint2*)(g_Plo + R * 512);
#pragma unroll
    for (int i = 0; i < 4; ++i) {
        float e0 = v[4 * i] * inv, e1 = v[4 * i + 1] * inv, e2 = v[4 * i + 2] * inv, e3 = v[4 * i + 3] * inv;
        bf16 h0 = __float2bfloat16(e0), h1 = __float2bfloat16(e1);
        bf16 h2 = __float2bfloat16(e2), h3 = __float2bfloat16(e3);
        uint2 hv, lv;
        hv.x = ((u32)__bfloat16_as_ushort(h1) << 16) | __bfloat16_as_ushort(h0);
        hv.y = ((u32)__bfloat16_as_ushort(h3) << 16) | __bfloat16_as_ushort(h2);
        lv.x = pk2(e1 - __bfloat162float(h1), e0 - __bfloat162float(h0));
        lv.y = pk2(e3 - __bfloat162float(h3), e2 - __bfloat162float(h2));
        Ph[i * 32 + lane] = hv;
        Pl[i * 32 + lane] = lv;
    }
}

// out = P @ V, cols 0..255 (CTA 128x256, no col guard needed)
__global__ __launch_bounds__(256) void out_kernel256(float* __restrict__ out) {
    extern __shared__ char sm[];
    const u32 sb = s2u(sm);
    const int lane = threadIdx.x & 31, wid = threadIdx.x >> 5;
    const int wm = wid >> 2, wn = wid & 3;
    const int t0 = blockIdx.x * 128;
    const int b = blockIdx.z & 15, h = blockIdx.z >> 4, hb = h * 16 + b;
    float acc[4][8][4]; ACC_ZERO(acc, 4);
    gemm3<8, 4>(sb,
                g_Phi + ((size_t)hb * 2048 + t0) * 512, g_Plo + ((size_t)hb * 2048 + t0) * 512,
                g_Vhi + (size_t)b * 384 * 512,          g_Vlo + (size_t)b * 384 * 512,
                512, acc);
#pragma unroll
    for (int mi = 0; mi < 4; ++mi)
#pragma unroll
        for (int ni = 0; ni < 8; ++ni) {
            int row = t0 + wm * 64 + mi * 16 + (lane >> 2);
            int col = wn * 64 + ni * 8 + 2 * (lane & 3);
            *(float2*)&out[((size_t)hb * 2048 + row) * 300 + col] =
                make_float2(acc[mi][ni][0], acc[mi][ni][1]);
            *(float2*)&out[((size_t)hb * 2048 + row + 8) * 300 + col] =
                make_float2(acc[mi][ni][2], acc[mi][ni][3]);
        }
}

// out = P @ V, cols 256..319 (CTA 128x64, store col<300)
__global__ __launch_bounds__(256) void out_kernel64(float* __restrict__ out) {
    extern __shared__ char sm[];
    const u32 sb = s2u(sm);
    const int lane = threadIdx.x & 31, wid = threadIdx.x >> 5;
    const int wm = wid >> 2, wn = wid & 3;
    const int t0 = blockIdx.x * 128;
    const int b = blockIdx.z & 15, h = blockIdx.z >> 4, hb = h * 16 + b;
    float acc[4][2][4]; ACC_ZERO(acc, 1);
    gemm3<8, 1>(sb,
                g_Phi + ((size_t)hb * 2048 + t0) * 512, g_Plo + ((size_t)hb * 2048 + t0) * 512,
                g_Vhi + ((size_t)b * 384 + 256) * 512,  g_Vlo + ((size_t)b * 384 + 256) * 512,
                512, acc);
#pragma unroll
    for (int mi = 0; mi < 4; ++mi)
#pragma unroll
        for (int ni = 0; ni < 2; ++ni) {
            int row = t0 + wm * 64 + mi * 16 + (lane >> 2);
            int col = 256 + wn * 16 + ni * 8 + 2 * (lane & 3);
            if (col < 300) {
                *(float2*)&out[((size_t)hb * 2048 + row) * 300 + col] =
                    make_float2(acc[mi][ni][0], acc[mi][ni][1]);
                *(float2*)&out[((size_t)hb * 2048 + row + 8) * 300 + col] =
                    make_float2(acc[mi][ni][2], acc[mi][ni][3]);
            }
        }
}

extern "C" void kernel_launch(void* const* d_in, const int* in_sizes, int n_in,
                              void* d_out, int out_size) {
    (void)in_sizes; (void)n_in; (void)out_size;
    const float* in1 = (const float*)d_in[0];
    const float* in2 = (const float*)d_in[1];
    const float* W2  = (const float*)d_in[2];
    const float* b2  = (const float*)d_in[3];
    const float* W3  = (const float*)d_in[4];
    const float* b3  = (const float*)d_in[5];
    float* out = (float*)d_out;

    split_in1<<<(int)((16L * 2048 * KP + 255) / 256), 256>>>(in1);
    split_in2<<<(int)((16L * 512 * KP + 255) / 256), 256>>>(in2);
    wsplit_kernel<<<(2 * 300 * 300 + 255) / 256, 256>>>(W2, W3);
    vt_kernel<<<dim3(16, 12, 16), dim3(32, 8)>>>(in2);

    cudaFuncSetAttribute(proj_mma, cudaFuncAttributeMaxDynamicSharedMemorySize, SMEM_GN2);
    proj_mma<<<dim3(64, 3, 2), 256, SMEM_GN2>>>(b2, b3);

    cudaFuncSetAttribute(scores_kernel, cudaFuncAttributeMaxDynamicSharedMemorySize, SMEM_GN4);
    scores_kernel<<<dim3(16, 2, 32), 256, SMEM_GN4>>>();

    softmax_kernel<<<8192, 256>>>();

    cudaFuncSetAttribute(out_kernel256, cudaFuncAttributeMaxDynamicSharedMemorySize, SMEM_GN4);
    out_kernel256<<<dim3(16, 1, 32), 256, SMEM_GN4>>>(out);

    cudaFuncSetAttribute(out_kernel64, cudaFuncAttributeMaxDynamicSharedMemorySize, SMEM_GN1);
    out_kernel64<<<dim3(16, 1, 32), 256, SMEM_GN1>>>(out);
}

// round 9
// speedup vs baseline: 4.6797x; 1.0153x over previous
#include <cuda_runtime.h>
#include <cuda_bf16.h>
#include <cstdint>

typedef unsigned long long ull;
typedef unsigned int u32;
typedef __nv_bfloat16 bf16;

// ---------- cp.async ----------
__device__ __forceinline__ void cpa16(u32 d, const void* s) {
    asm volatile("cp.async.cg.shared.global [%0], [%1], 16;" :: "r"(d), "l"(s));
}
#define CP_COMMIT() asm volatile("cp.async.commit_group;")
// ---------- mma.sync / ldmatrix ----------
__device__ __forceinline__ u32 s2u(const void* p) { return (u32)__cvta_generic_to_shared(p); }
__device__ __forceinline__ void ldsm4(u32* r, u32 a) {
    asm volatile("ldmatrix.sync.aligned.m8n8.x4.shared.b16 {%0,%1,%2,%3}, [%4];"
                 : "=r"(r[0]), "=r"(r[1]), "=r"(r[2]), "=r"(r[3]) : "r"(a));
}
__device__ __forceinline__ void mma16816(float* c, const u32* a, u32 b0, u32 b1) {
    asm volatile("mma.sync.aligned.m16n8k16.row.col.f32.bf16.bf16.f32 "
                 "{%0,%1,%2,%3}, {%4,%5,%6,%7}, {%8,%9}, {%0,%1,%2,%3};"
                 : "+f"(c[0]), "+f"(c[1]), "+f"(c[2]), "+f"(c[3])
                 : "r"(a[0]), "r"(a[1]), "r"(a[2]), "r"(a[3]), "r"(b0), "r"(b1));
}
__device__ __forceinline__ u32 pk2(float up, float lo) {
    u32 d; asm("cvt.rn.bf16x2.f32 %0, %1, %2;" : "=r"(d) : "f"(up), "f"(lo)); return d;
}

#define KP 320
__device__ float g_S[2L * 16 * 2048 * 512];
__device__ bf16 g_Ahi[16L * 2048 * KP], g_Alo[16L * 2048 * KP];
__device__ bf16 g_I2hi[16L * 512 * KP], g_I2lo[16L * 512 * KP];
__device__ bf16 g_Wsphi[2L * 384 * KP], g_Wsplo[2L * 384 * KP];       // pads zero-init
__device__ bf16 g_Whi[2L * 16 * 512 * KP], g_Wlo[2L * 16 * 512 * KP]; // cols>=300 zero-init
__device__ bf16 g_Vhi[16L * 384 * 512],  g_Vlo[16L * 384 * 512];
__device__ bf16 g_Phi[2L * 16 * 2048 * 512], g_Plo[2L * 16 * 2048 * 512];

// stage rows x 64-col bf16 tile (128B rows), XOR swizzle; 256 threads
__device__ __forceinline__ void ldt(u32 dst, const bf16* src, int pitch, int k0, int rows) {
    for (int i = threadIdx.x; i < rows * 8; i += 256) {
        int r = i >> 3, c = i & 7;
        cpa16(dst + r * 128 + ((c ^ (r & 7)) << 4), src + (size_t)r * pitch + k0 + c * 8);
    }
}

__global__ void split_in1(const float* __restrict__ in1) {
    size_t i = (size_t)blockIdx.x * 256 + threadIdx.x;
    if (i >= 16L * 2048 * KP) return;
    int k = (int)(i % KP); size_t bt = i / KP;
    float v = (k < 300) ? in1[bt * 300 + k] : 0.f;
    bf16 h = __float2bfloat16(v);
    g_Ahi[i] = h; g_Alo[i] = __float2bfloat16(v - __bfloat162float(h));
}

__global__ void split_in2(const float* __restrict__ in2) {
    size_t i = (size_t)blockIdx.x * 256 + threadIdx.x;
    if (i >= 16L * 512 * KP) return;
    int k = (int)(i % KP); size_t bw = i / KP;
    float v = (k < 300) ? in2[bw * 300 + k] : 0.f;
    bf16 h = __float2bfloat16(v);
    g_I2hi[i] = h; g_I2lo[i] = __float2bfloat16(v - __bfloat162float(h));
}

__global__ void wsplit_kernel(const float* __restrict__ W2, const float* __restrict__ W3) {
    int idx = blockIdx.x * blockDim.x + threadIdx.x;
    if (idx >= 2 * 300 * 300) return;
    int h = idx / (300 * 300), rem = idx - h * (300 * 300);
    int e = rem / 300, d = rem - e * 300;
    float v = (h ? W3 : W2)[e * 300 + d];
    bf16 hi = __float2bfloat16(v);
    size_t o = ((size_t)h * 384 + e) * KP + d;
    g_Wsphi[o] = hi; g_Wsplo[o] = __float2bfloat16(v - __bfloat162float(hi));
}

__global__ void vt_kernel(const float* __restrict__ in2) {
    __shared__ float t[32][33];
    const int b = blockIdx.z, d0 = blockIdx.y * 32, w0 = blockIdx.x * 32;
    const int tx = threadIdx.x, ty = threadIdx.y;
    for (int yy = ty; yy < 32; yy += 8)
        t[yy][tx] = (d0 + tx < 300) ? in2[((size_t)b * 512 + w0 + yy) * 300 + d0 + tx] : 0.f;
    __syncthreads();
    for (int yy = ty; yy < 32; yy += 8) {
        float v = t[tx][yy];
        bf16 hi = __float2bfloat16(v);
        size_t o = ((size_t)b * 384 + d0 + yy) * 512 + w0 + tx;
        g_Vhi[o] = hi; g_Vlo[o] = __float2bfloat16(v - __bfloat162float(hi));
    }
}

// ========== mma.sync GEMM core: CTA 128 x (64*GN), warp 64 x (16*GN), 2-stage ==========
template<int NCHUNK, int GN>
__device__ __forceinline__ void gemm3(u32 sb, const bf16* Ah, const bf16* Al,
                                      const bf16* Bh, const bf16* Bl,
                                      int pitch, float acc[4][2 * GN][4]) {
    constexpr int BN = 64 * GN;
    constexpr u32 ASZ = 128 * 128;          // 16 KB per A half
    constexpr u32 BSZ = (u32)BN * 128;
    constexpr u32 STAGE = 2 * ASZ + 2 * BSZ;
    const int lane = threadIdx.x & 31, wid = threadIdx.x >> 5;
    const int wm = wid >> 2, wn = wid & 3;
    ldt(sb, Ah, pitch, 0, 128);             ldt(sb + ASZ, Al, pitch, 0, 128);
    ldt(sb + 2 * ASZ, Bh, pitch, 0, BN);    ldt(sb + 2 * ASZ + BSZ, Bl, pitch, 0, BN);
    CP_COMMIT();
    const int rA = wm * 64 + (lane & 15), rB = wn * (GN * 16) + (lane & 15);
    const int chalf = lane >> 4;
    for (int kc = 0; kc < NCHUNK; ++kc) {
        if (kc + 1 < NCHUNK) {
            u32 d = sb + ((kc + 1) & 1) * STAGE;
            int k0 = (kc + 1) * 64;
            ldt(d, Ah, pitch, k0, 128);          ldt(d + ASZ, Al, pitch, k0, 128);
            ldt(d + 2 * ASZ, Bh, pitch, k0, BN); ldt(d + 2 * ASZ + BSZ, Bl, pitch, k0, BN);
            CP_COMMIT();
            asm volatile("cp.async.wait_group 1;");
        } else {
            asm volatile("cp.async.wait_group 0;");
        }
        __syncthreads();
        u32 st = sb + (kc & 1) * STAGE;
#pragma unroll
        for (int ks = 0; ks < 4; ++ks) {
            const int c16 = ks * 2 + chalf;
            const u32 offA = rA * 128 + (((u32)(c16 ^ (rA & 7))) << 4);
            const u32 offB = rB * 128 + (((u32)(c16 ^ (rB & 7))) << 4);
            u32 ah[4][4], al[4][4], bh[GN][4], bl[GN][4];
#pragma unroll
            for (int mi = 0; mi < 4; ++mi) {
                ldsm4(ah[mi], st + offA + mi * 2048);
                ldsm4(al[mi], st + ASZ + offA + mi * 2048);
            }
#pragma unroll
            for (int g = 0; g < GN; ++g) {
                ldsm4(bh[g], st + 2 * ASZ + offB + g * 2048);
                ldsm4(bl[g], st + 2 * ASZ + BSZ + offB + g * 2048);
            }
#pragma unroll
            for (int mi = 0; mi < 4; ++mi)
#pragma unroll
                for (int g = 0; g < GN; ++g)
#pragma unroll
                    for (int sub = 0; sub < 2; ++sub) {
                        float* c = acc[mi][g * 2 + sub];
                        mma16816(c, ah[mi], bh[g][sub], bh[g][sub + 2]);
                        mma16816(c, ah[mi], bl[g][sub], bl[g][sub + 2]);
                        mma16816(c, al[mi], bh[g][sub], bh[g][sub + 2]);
                    }
        }
        __syncthreads();
    }
}

#define SMEM_GN5 229376
#define SMEM_GN4 196608
#define SMEM_GN2 131072
#define ACC_ZERO(acc, GN) do { _Pragma("unroll") for (int _i = 0; _i < 4; ++_i) \
    _Pragma("unroll") for (int _j = 0; _j < 2 * (GN); ++_j) \
    _Pragma("unroll") for (int _q = 0; _q < 4; ++_q) acc[_i][_j][_q] = 0.f; } while (0)

// proj = in2 @ W^T + b -> g_Whi/g_Wlo ([h*8192 + b*512 + w][e])
__global__ __launch_bounds__(256) void proj_mma(const float* __restrict__ b2,
                                                const float* __restrict__ b3) {
    extern __shared__ char sm[];
    const u32 sb = s2u(sm);
    const int lane = threadIdx.x & 31, wid = threadIdx.x >> 5;
    const int wm = wid >> 2, wn = wid & 3;
    const int t0 = blockIdx.x * 128, n0 = blockIdx.y * 128, h = blockIdx.z;
    float acc[4][4][4]; ACC_ZERO(acc, 2);
    gemm3<5, 2>(sb, g_I2hi + (size_t)t0 * KP, g_I2lo + (size_t)t0 * KP,
                g_Wsphi + ((size_t)h * 384 + n0) * KP, g_Wsplo + ((size_t)h * 384 + n0) * KP,
                KP, acc);
    const float* bias = h ? b3 : b2;
    bf16* Whi = g_Whi + (size_t)h * 8192 * KP;
    bf16* Wlo = g_Wlo + (size_t)h * 8192 * KP;
#pragma unroll
    for (int mi = 0; mi < 4; ++mi)
#pragma unroll
        for (int ni = 0; ni < 4; ++ni) {
            int row = t0 + wm * 64 + mi * 16 + (lane >> 2);
            int col = n0 + wn * 32 + ni * 8 + 2 * (lane & 3);
            if (col < 300) {
                float bc0 = bias[col], bc1 = bias[col + 1];
#pragma unroll
                for (int half = 0; half < 2; ++half) {
                    int r = row + half * 8;
                    float v0 = acc[mi][ni][2 * half] + bc0;
                    float v1 = acc[mi][ni][2 * half + 1] + bc1;
                    bf16 h0 = __float2bfloat16(v0), h1 = __float2bfloat16(v1);
                    u32 hp = ((u32)__bfloat16_as_ushort(h1) << 16) | __bfloat16_as_ushort(h0);
                    u32 lp = pk2(v1 - __bfloat162float(h1), v0 - __bfloat162float(h0));
                    *(u32*)&Whi[(size_t)r * KP + col] = hp;
                    *(u32*)&Wlo[(size_t)r * KP + col] = lp;
                }
            }
        }
}

// scores: S[t][w] fp32, CTA 128x256, smem-staged coalesced stores
__global__ __launch_bounds__(256) void scores_kernel() {
    extern __shared__ char sm[];
    const u32 sb = s2u(sm);
    const int tid = threadIdx.x;
    const int lane = tid & 31, wid = tid >> 5;
    const int wm = wid >> 2, wn = wid & 3;
    const int t0 = blockIdx.x * 128, w0 = blockIdx.y * 256;
    const int b = blockIdx.z & 15, h = blockIdx.z >> 4, hb = h * 16 + b;
    float acc[4][8][4]; ACC_ZERO(acc, 4);
    gemm3<5, 4>(sb,
                g_Ahi + ((size_t)b * 2048 + t0) * KP, g_Alo + ((size_t)b * 2048 + t0) * KP,
                g_Whi + ((size_t)hb * 512 + w0) * KP, g_Wlo + ((size_t)hb * 512 + w0) * KP,
                KP, acc);
    // stage to smem [128][264], then coalesced float4 stores
    float* stg = (float*)sm;
#pragma unroll
    for (int mi = 0; mi < 4; ++mi)
#pragma unroll
        for (int ni = 0; ni < 8; ++ni) {
            int r = wm * 64 + mi * 16 + (lane >> 2);
            int c = wn * 64 + ni * 8 + 2 * (lane & 3);
            *(float2*)&stg[r * 264 + c]       = make_float2(acc[mi][ni][0], acc[mi][ni][1]);
            *(float2*)&stg[(r + 8) * 264 + c] = make_float2(acc[mi][ni][2], acc[mi][ni][3]);
        }
    __syncthreads();
    float* S = g_S + (size_t)hb * 2048 * 512;
    for (int i = tid; i < 128 * 64; i += 256) {
        int r = i >> 6, c4 = (i & 63) * 4;
        *(float4*)&S[(size_t)(t0 + r) * 512 + w0 + c4] = *(float4*)&stg[r * 264 + c4];
    }
}

// softmax: warp per row -> P hi/lo bf16
__global__ __launch_bounds__(256) void softmax_kernel() {
    const int lane = threadIdx.x & 31;
    const size_t R = (size_t)blockIdx.x * 8 + (threadIdx.x >> 5);
    const float4* Srow = (const float4*)(g_S + R * 512);
    float v[16];
#pragma unroll
    for (int i = 0; i < 4; ++i) {
        float4 q = Srow[i * 32 + lane];
        v[4 * i] = q.x; v[4 * i + 1] = q.y; v[4 * i + 2] = q.z; v[4 * i + 3] = q.w;
    }
    float m = v[0];
#pragma unroll
    for (int i = 1; i < 16; ++i) m = fmaxf(m, v[i]);
#pragma unroll
    for (int o = 16; o; o >>= 1) m = fmaxf(m, __shfl_xor_sync(0xffffffffu, m, o));
    float s = 0.f;
#pragma unroll
    for (int i = 0; i < 16; ++i) { v[i] = __expf(v[i] - m); s += v[i]; }
#pragma unroll
    for (int o = 16; o; o >>= 1) s += __shfl_xor_sync(0xffffffffu, s, o);
    const float inv = 1.f / s;
    uint2* Ph = (uint2*)(g_Phi + R * 512);
    uint2* Pl = (uint2*)(g_Plo + R * 512);
#pragma unroll
    for (int i = 0; i < 4; ++i) {
        float e0 = v[4 * i] * inv, e1 = v[4 * i + 1] * inv, e2 = v[4 * i + 2] * inv, e3 = v[4 * i + 3] * inv;
        bf16 h0 = __float2bfloat16(e0), h1 = __float2bfloat16(e1);
        bf16 h2 = __float2bfloat16(e2), h3 = __float2bfloat16(e3);
        uint2 hv, lv;
        hv.x = ((u32)__bfloat16_as_ushort(h1) << 16) | __bfloat16_as_ushort(h0);
        hv.y = ((u32)__bfloat16_as_ushort(h3) << 16) | __bfloat16_as_ushort(h2);
        lv.x = pk2(e1 - __bfloat162float(h1), e0 - __bfloat162float(h0));
        lv.y = pk2(e3 - __bfloat162float(h3), e2 - __bfloat162float(h2));
        Ph[i * 32 + lane] = hv;
        Pl[i * 32 + lane] = lv;
    }
}

// out = P @ V, all 320 cols in ONE kernel (CTA 128x320), smem-staged stores
__global__ __launch_bounds__(256) void out_kernel(float* __restrict__ out) {
    extern __shared__ char sm[];
    const u32 sb = s2u(sm);
    const int tid = threadIdx.x;
    const int lane = tid & 31, wid = tid >> 5;
    const int wm = wid >> 2, wn = wid & 3;
    const int t0 = blockIdx.x * 128;
    const int b = blockIdx.z & 15, h = blockIdx.z >> 4, hb = h * 16 + b;
    float acc[4][10][4]; ACC_ZERO(acc, 5);
    gemm3<8, 5>(sb,
                g_Phi + ((size_t)hb * 2048 + t0) * 512, g_Plo + ((size_t)hb * 2048 + t0) * 512,
                g_Vhi + (size_t)b * 384 * 512,          g_Vlo + (size_t)b * 384 * 512,
                512, acc);
    // stage [128][328] floats, then coalesced float4 stores of cols 0..299
    float* stg = (float*)sm;
#pragma unroll
    for (int mi = 0; mi < 4; ++mi)
#pragma unroll
        for (int ni = 0; ni < 10; ++ni) {
            int r = wm * 64 + mi * 16 + (lane >> 2);
            int c = wn * 80 + ni * 8 + 2 * (lane & 3);
            *(float2*)&stg[r * 328 + c]       = make_float2(acc[mi][ni][0], acc[mi][ni][1]);
            *(float2*)&stg[(r + 8) * 328 + c] = make_float2(acc[mi][ni][2], acc[mi][ni][3]);
        }
    __syncthreads();
    for (int i = tid; i < 128 * 75; i += 256) {
        int r = i / 75, c = (i - r * 75) * 4;
        *(float4*)&out[((size_t)hb * 2048 + t0 + r) * 300 + c] = *(float4*)&stg[r * 328 + c];
    }
}

extern "C" void kernel_launch(void* const* d_in, const int* in_sizes, int n_in,
                              void* d_out, int out_size) {
    (void)in_sizes; (void)n_in; (void)out_size;
    const float* in1 = (const float*)d_in[0];
    const float* in2 = (const float*)d_in[1];
    const float* W2  = (const float*)d_in[2];
    const float* b2  = (const float*)d_in[3];
    const float* W3  = (const float*)d_in[4];
    const float* b3  = (const float*)d_in[5];
    float* out = (float*)d_out;

    split_in1<<<(int)((16L * 2048 * KP + 255) / 256), 256>>>(in1);
    split_in2<<<(int)((16L * 512 * KP + 255) / 256), 256>>>(in2);
    wsplit_kernel<<<(2 * 300 * 300 + 255) / 256, 256>>>(W2, W3);
    vt_kernel<<<dim3(16, 10, 16), dim3(32, 8)>>>(in2);

    cudaFuncSetAttribute(proj_mma, cudaFuncAttributeMaxDynamicSharedMemorySize, SMEM_GN2);
    proj_mma<<<dim3(64, 3, 2), 256, SMEM_GN2>>>(b2, b3);

    cudaFuncSetAttribute(scores_kernel, cudaFuncAttributeMaxDynamicSharedMemorySize, SMEM_GN4);
    scores_kernel<<<dim3(16, 2, 32), 256, SMEM_GN4>>>();

    softmax_kernel<<<8192, 256>>>();

    cudaFuncSetAttribute(out_kernel, cudaFuncAttributeMaxDynamicSharedMemorySize, SMEM_GN5);
    out_kernel<<<dim3(16, 1, 32), 256, SMEM_GN5>>>(out);
}

// round 11
// speedup vs baseline: 6.1642x; 1.3172x over previous
#include <cuda_runtime.h>
#include <cuda_bf16.h>
#include <cuda_fp16.h>
#include <cstdint>

typedef unsigned long long ull;
typedef unsigned int u32;
typedef __nv_bfloat16 bf16;

// ---------- cp.async ----------
__device__ __forceinline__ void cpa16(u32 d, const void* s) {
    asm volatile("cp.async.cg.shared.global [%0], [%1], 16;" :: "r"(d), "l"(s));
}
#define CP_COMMIT() asm volatile("cp.async.commit_group;")
// ---------- mma.sync / ldmatrix ----------
__device__ __forceinline__ u32 s2u(const void* p) { return (u32)__cvta_generic_to_shared(p); }
__device__ __forceinline__ void ldsm4(u32* r, u32 a) {
    asm volatile("ldmatrix.sync.aligned.m8n8.x4.shared.b16 {%0,%1,%2,%3}, [%4];"
                 : "=r"(r[0]), "=r"(r[1]), "=r"(r[2]), "=r"(r[3]) : "r"(a));
}
__device__ __forceinline__ void mma16816(float* c, const u32* a, u32 b0, u32 b1) {
    asm volatile("mma.sync.aligned.m16n8k16.row.col.f32.bf16.bf16.f32 "
                 "{%0,%1,%2,%3}, {%4,%5,%6,%7}, {%8,%9}, {%0,%1,%2,%3};"
                 : "+f"(c[0]), "+f"(c[1]), "+f"(c[2]), "+f"(c[3])
                 : "r"(a[0]), "r"(a[1]), "r"(a[2]), "r"(a[3]), "r"(b0), "r"(b1));
}
__device__ __forceinline__ void mma16816h(float* c, const u32* a, u32 b0, u32 b1) {
    asm volatile("mma.sync.aligned.m16n8k16.row.col.f32.f16.f16.f32 "
                 "{%0,%1,%2,%3}, {%4,%5,%6,%7}, {%8,%9}, {%0,%1,%2,%3};"
                 : "+f"(c[0]), "+f"(c[1]), "+f"(c[2]), "+f"(c[3])
                 : "r"(a[0]), "r"(a[1]), "r"(a[2]), "r"(a[3]), "r"(b0), "r"(b1));
}
__device__ __forceinline__ u32 pk2(float up, float lo) {
    u32 d; asm("cvt.rn.bf16x2.f32 %0, %1, %2;" : "=r"(d) : "f"(up), "f"(lo)); return d;
}

#define KP 320
__device__ float g_S[2L * 16 * 2048 * 512];
__device__ bf16 g_Ahi[16L * 2048 * KP], g_Alo[16L * 2048 * KP];
__device__ bf16 g_I2hi[16L * 512 * KP], g_I2lo[16L * 512 * KP];
__device__ bf16 g_Wsphi[2L * 384 * KP], g_Wsplo[2L * 384 * KP];       // pads zero-init
__device__ bf16 g_Whi[2L * 16 * 512 * KP], g_Wlo[2L * 16 * 512 * KP]; // cols>=300 zero-init
__device__ __half g_V16[16L * 320 * 512];                              // rows 300..319 zero-init
__device__ __half g_P16[2L * 16 * 2048 * 512];

// stage rows x 64-col 16-bit tile (128B rows), XOR swizzle; 256 threads
__device__ __forceinline__ void ldt(u32 dst, const bf16* src, int pitch, int k0, int rows) {
    for (int i = threadIdx.x; i < rows * 8; i += 256) {
        int r = i >> 3, c = i & 7;
        cpa16(dst + r * 128 + ((c ^ (r & 7)) << 4), src + (size_t)r * pitch + k0 + c * 8);
    }
}

__global__ void split_in1(const float* __restrict__ in1) {
    size_t i = (size_t)blockIdx.x * 256 + threadIdx.x;
    if (i >= 16L * 2048 * KP) return;
    int k = (int)(i % KP); size_t bt = i / KP;
    float v = (k < 300) ? in1[bt * 300 + k] : 0.f;
    bf16 h = __float2bfloat16(v);
    g_Ahi[i] = h; g_Alo[i] = __float2bfloat16(v - __bfloat162float(h));
}

__global__ void split_in2(const float* __restrict__ in2) {
    size_t i = (size_t)blockIdx.x * 256 + threadIdx.x;
    if (i >= 16L * 512 * KP) return;
    int k = (int)(i % KP); size_t bw = i / KP;
    float v = (k < 300) ? in2[bw * 300 + k] : 0.f;
    bf16 h = __float2bfloat16(v);
    g_I2hi[i] = h; g_I2lo[i] = __float2bfloat16(v - __bfloat162float(h));
}

__global__ void wsplit_kernel(const float* __restrict__ W2, const float* __restrict__ W3) {
    int idx = blockIdx.x * blockDim.x + threadIdx.x;
    if (idx >= 2 * 300 * 300) return;
    int h = idx / (300 * 300), rem = idx - h * (300 * 300);
    int e = rem / 300, d = rem - e * 300;
    float v = (h ? W3 : W2)[e * 300 + d];
    bf16 hi = __float2bfloat16(v);
    size_t o = ((size_t)h * 384 + e) * KP + d;
    g_Wsphi[o] = hi; g_Wsplo[o] = __float2bfloat16(v - __bfloat162float(hi));
}

// V16[b][d][w] = fp16(in2[b][w][d]), d in [0,320), rows >=300 left zero
__global__ void vt_kernel(const float* __restrict__ in2) {
    __shared__ float t[32][33];
    const int b = blockIdx.z, d0 = blockIdx.y * 32, w0 = blockIdx.x * 32;
    const int tx = threadIdx.x, ty = threadIdx.y;
    for (int yy = ty; yy < 32; yy += 8)
        t[yy][tx] = (d0 + tx < 300) ? in2[((size_t)b * 512 + w0 + yy) * 300 + d0 + tx] : 0.f;
    __syncthreads();
    for (int yy = ty; yy < 32; yy += 8)
        g_V16[((size_t)b * 320 + d0 + yy) * 512 + w0 + tx] = __float2half(t[tx][yy]);
}

// ========== 3-product bf16 GEMM core (scores/proj): CTA 128 x (64*GN), 2-stage ==========
template<int NCHUNK, int GN>
__device__ __forceinline__ void gemm3(u32 sb, const bf16* Ah, const bf16* Al,
                                      const bf16* Bh, const bf16* Bl,
                                      int pitch, float acc[4][2 * GN][4]) {
    constexpr int BN = 64 * GN;
    constexpr u32 ASZ = 128 * 128;
    constexpr u32 BSZ = (u32)BN * 128;
    constexpr u32 STAGE = 2 * ASZ + 2 * BSZ;
    const int lane = threadIdx.x & 31, wid = threadIdx.x >> 5;
    const int wm = wid >> 2, wn = wid & 3;
    ldt(sb, Ah, pitch, 0, 128);             ldt(sb + ASZ, Al, pitch, 0, 128);
    ldt(sb + 2 * ASZ, Bh, pitch, 0, BN);    ldt(sb + 2 * ASZ + BSZ, Bl, pitch, 0, BN);
    CP_COMMIT();
    const int rA = wm * 64 + (lane & 15), rB = wn * (GN * 16) + (lane & 15);
    const int chalf = lane >> 4;
    for (int kc = 0; kc < NCHUNK; ++kc) {
        if (kc + 1 < NCHUNK) {
            u32 d = sb + ((kc + 1) & 1) * STAGE;
            int k0 = (kc + 1) * 64;
            ldt(d, Ah, pitch, k0, 128);          ldt(d + ASZ, Al, pitch, k0, 128);
            ldt(d + 2 * ASZ, Bh, pitch, k0, BN); ldt(d + 2 * ASZ + BSZ, Bl, pitch, k0, BN);
            CP_COMMIT();
            asm volatile("cp.async.wait_group 1;");
        } else {
            asm volatile("cp.async.wait_group 0;");
        }
        __syncthreads();
        u32 st = sb + (kc & 1) * STAGE;
#pragma unroll
        for (int ks = 0; ks < 4; ++ks) {
            const int c16 = ks * 2 + chalf;
            const u32 offA = rA * 128 + (((u32)(c16 ^ (rA & 7))) << 4);
            const u32 offB = rB * 128 + (((u32)(c16 ^ (rB & 7))) << 4);
            u32 ah[4][4], al[4][4], bh[GN][4], bl[GN][4];
#pragma unroll
            for (int mi = 0; mi < 4; ++mi) {
                ldsm4(ah[mi], st + offA + mi * 2048);
                ldsm4(al[mi], st + ASZ + offA + mi * 2048);
            }
#pragma unroll
            for (int g = 0; g < GN; ++g) {
                ldsm4(bh[g], st + 2 * ASZ + offB + g * 2048);
                ldsm4(bl[g], st + 2 * ASZ + BSZ + offB + g * 2048);
            }
#pragma unroll
            for (int mi = 0; mi < 4; ++mi)
#pragma unroll
                for (int g = 0; g < GN; ++g)
#pragma unroll
                    for (int sub = 0; sub < 2; ++sub) {
                        float* c = acc[mi][g * 2 + sub];
                        mma16816(c, ah[mi], bh[g][sub], bh[g][sub + 2]);
                        mma16816(c, ah[mi], bl[g][sub], bl[g][sub + 2]);
                        mma16816(c, al[mi], bh[g][sub], bh[g][sub + 2]);
                    }
        }
        __syncthreads();
    }
}

// ========== single-product fp16 GEMM core (out): CTA 128 x (64*GN), 2-stage ==========
template<int NCHUNK, int GN>
__device__ __forceinline__ void gemm1(u32 sb, const bf16* A, const bf16* B,
                                      int pitch, float acc[4][2 * GN][4]) {
    constexpr int BN = 64 * GN;
    constexpr u32 ASZ = 128 * 128;
    constexpr u32 BSZ = (u32)BN * 128;
    constexpr u32 STAGE = ASZ + BSZ;
    const int lane = threadIdx.x & 31, wid = threadIdx.x >> 5;
    const int wm = wid >> 2, wn = wid & 3;
    ldt(sb, A, pitch, 0, 128);
    ldt(sb + ASZ, B, pitch, 0, BN);
    CP_COMMIT();
    const int rA = wm * 64 + (lane & 15), rB = wn * (GN * 16) + (lane & 15);
    const int chalf = lane >> 4;
    for (int kc = 0; kc < NCHUNK; ++kc) {
        if (kc + 1 < NCHUNK) {
            u32 d = sb + ((kc + 1) & 1) * STAGE;
            int k0 = (kc + 1) * 64;
            ldt(d, A, pitch, k0, 128);
            ldt(d + ASZ, B, pitch, k0, BN);
            CP_COMMIT();
            asm volatile("cp.async.wait_group 1;");
        } else {
            asm volatile("cp.async.wait_group 0;");
        }
        __syncthreads();
        u32 st = sb + (kc & 1) * STAGE;
#pragma unroll
        for (int ks = 0; ks < 4; ++ks) {
            const int c16 = ks * 2 + chalf;
            const u32 offA = rA * 128 + (((u32)(c16 ^ (rA & 7))) << 4);
            const u32 offB = rB * 128 + (((u32)(c16 ^ (rB & 7))) << 4);
            u32 ah[4][4], bh[GN][4];
#pragma unroll
            for (int mi = 0; mi < 4; ++mi) ldsm4(ah[mi], st + offA + mi * 2048);
#pragma unroll
            for (int g = 0; g < GN; ++g)  ldsm4(bh[g], st + ASZ + offB + g * 2048);
#pragma unroll
            for (int mi = 0; mi < 4; ++mi)
#pragma unroll
                for (int g = 0; g < GN; ++g)
#pragma unroll
                    for (int sub = 0; sub < 2; ++sub)
                        mma16816h(acc[mi][g * 2 + sub], ah[mi], bh[g][sub], bh[g][sub + 2]);
        }
        __syncthreads();
    }
}

#define SMEM_GN4 196608
#define SMEM_GN2 131072
#define SMEM_OUT 172032
#define ACC_ZERO(acc, GN) do { _Pragma("unroll") for (int _i = 0; _i < 4; ++_i) \
    _Pragma("unroll") for (int _j = 0; _j < 2 * (GN); ++_j) \
    _Pragma("unroll") for (int _q = 0; _q < 4; ++_q) acc[_i][_j][_q] = 0.f; } while (0)

// proj = in2 @ W^T + b -> g_Whi/g_Wlo ([h*8192 + b*512 + w][e])
__global__ __launch_bounds__(256) void proj_mma(const float* __restrict__ b2,
                                                const float* __restrict__ b3) {
    extern __shared__ char sm[];
    const u32 sb = s2u(sm);
    const int lane = threadIdx.x & 31, wid = threadIdx.x >> 5;
    const int wm = wid >> 2, wn = wid & 3;
    const int t0 = blockIdx.x * 128, n0 = blockIdx.y * 128, h = blockIdx.z;
    float acc[4][4][4]; ACC_ZERO(acc, 2);
    gemm3<5, 2>(sb, g_I2hi + (size_t)t0 * KP, g_I2lo + (size_t)t0 * KP,
                g_Wsphi + ((size_t)h * 384 + n0) * KP, g_Wsplo + ((size_t)h * 384 + n0) * KP,
                KP, acc);
    const float* bias = h ? b3 : b2;
    bf16* Whi = g_Whi + (size_t)h * 8192 * KP;
    bf16* Wlo = g_Wlo + (size_t)h * 8192 * KP;
#pragma unroll
    for (int mi = 0; mi < 4; ++mi)
#pragma unroll
        for (int ni = 0; ni < 4; ++ni) {
            int row = t0 + wm * 64 + mi * 16 + (lane >> 2);
            int col = n0 + wn * 32 + ni * 8 + 2 * (lane & 3);
            if (col < 300) {
                float bc0 = bias[col], bc1 = bias[col + 1];
#pragma unroll
                for (int half = 0; half < 2; ++half) {
                    int r = row + half * 8;
                    float v0 = acc[mi][ni][2 * half] + bc0;
                    float v1 = acc[mi][ni][2 * half + 1] + bc1;
                    bf16 h0 = __float2bfloat16(v0), h1 = __float2bfloat16(v1);
                    u32 hp = ((u32)__bfloat16_as_ushort(h1) << 16) | __bfloat16_as_ushort(h0);
                    u32 lp = pk2(v1 - __bfloat162float(h1), v0 - __bfloat162float(h0));
                    *(u32*)&Whi[(size_t)r * KP + col] = hp;
                    *(u32*)&Wlo[(size_t)r * KP + col] = lp;
                }
            }
        }
}

// scores: S[t][w] fp32, CTA 128x256, smem-staged coalesced stores
__global__ __launch_bounds__(256) void scores_kernel() {
    extern __shared__ char sm[];
    const u32 sb = s2u(sm);
    const int tid = threadIdx.x;
    const int lane = tid & 31, wid = tid >> 5;
    const int wm = wid >> 2, wn = wid & 3;
    const int t0 = blockIdx.x * 128, w0 = blockIdx.y * 256;
    const int b = blockIdx.z & 15, h = blockIdx.z >> 4, hb = h * 16 + b;
    float acc[4][8][4]; ACC_ZERO(acc, 4);
    gemm3<5, 4>(sb,
                g_Ahi + ((size_t)b * 2048 + t0) * KP, g_Alo + ((size_t)b * 2048 + t0) * KP,
                g_Whi + ((size_t)hb * 512 + w0) * KP, g_Wlo + ((size_t)hb * 512 + w0) * KP,
                KP, acc);
    float* stg = (float*)sm;
#pragma unroll
    for (int mi = 0; mi < 4; ++mi)
#pragma unroll
        for (int ni = 0; ni < 8; ++ni) {
            int r = wm * 64 + mi * 16 + (lane >> 2);
            int c = wn * 64 + ni * 8 + 2 * (lane & 3);
            *(float2*)&stg[r * 264 + c]       = make_float2(acc[mi][ni][0], acc[mi][ni][1]);
            *(float2*)&stg[(r + 8) * 264 + c] = make_float2(acc[mi][ni][2], acc[mi][ni][3]);
        }
    __syncthreads();
    float* S = g_S + (size_t)hb * 2048 * 512;
    for (int i = tid; i < 128 * 64; i += 256) {
        int r = i >> 6, c4 = (i & 63) * 4;
        *(float4*)&S[(size_t)(t0 + r) * 512 + w0 + c4] = *(float4*)&stg[r * 264 + c4];
    }
}

// softmax: warp per row -> P fp16
__global__ __launch_bounds__(256) void softmax_kernel() {
    const int lane = threadIdx.x & 31;
    const size_t R = (size_t)blockIdx.x * 8 + (threadIdx.x >> 5);
    const float4* Srow = (const float4*)(g_S + R * 512);
    float v[16];
#pragma unroll
    for (int i = 0; i < 4; ++i) {
        float4 q = Srow[i * 32 + lane];
        v[4 * i] = q.x; v[4 * i + 1] = q.y; v[4 * i + 2] = q.z; v[4 * i + 3] = q.w;
    }
    float m = v[0];
#pragma unroll
    for (int i = 1; i < 16; ++i) m = fmaxf(m, v[i]);
#pragma unroll
    for (int o = 16; o; o >>= 1) m = fmaxf(m, __shfl_xor_sync(0xffffffffu, m, o));
    float s = 0.f;
#pragma unroll
    for (int i = 0; i < 16; ++i) { v[i] = __expf(v[i] - m); s += v[i]; }
#pragma unroll
    for (int o = 16; o; o >>= 1) s += __shfl_xor_sync(0xffffffffu, s, o);
    const float inv = 1.f / s;
    __half2* P = (__half2*)(g_P16 + R * 512);
#pragma unroll
    for (int i = 0; i < 4; ++i) {
        int base = (i * 32 + lane) * 2;
        P[base]     = __floats2half2_rn(v[4 * i] * inv,     v[4 * i + 1] * inv);
        P[base + 1] = __floats2half2_rn(v[4 * i + 2] * inv, v[4 * i + 3] * inv);
    }
}

// out = P @ V (single fp16 product), CTA 128x320, smem-staged stores
__global__ __launch_bounds__(256) void out_kernel(float* __restrict__ out) {
    extern __shared__ char sm[];
    const u32 sb = s2u(sm);
    const int tid = threadIdx.x;
    const int lane = tid & 31, wid = tid >> 5;
    const int wm = wid >> 2, wn = wid & 3;
    const int t0 = blockIdx.x * 128;
    const int b = blockIdx.z & 15, h = blockIdx.z >> 4, hb = h * 16 + b;
    float acc[4][10][4]; ACC_ZERO(acc, 5);
    gemm1<8, 5>(sb,
                (const bf16*)(g_P16 + ((size_t)hb * 2048 + t0) * 512),
                (const bf16*)(g_V16 + (size_t)b * 320 * 512),
                512, acc);
    float* stg = (float*)sm;
#pragma unroll
    for (int mi = 0; mi < 4; ++mi)
#pragma unroll
        for (int ni = 0; ni < 10; ++ni) {
            int r = wm * 64 + mi * 16 + (lane >> 2);
            int c = wn * 80 + ni * 8 + 2 * (lane & 3);
            *(float2*)&stg[r * 328 + c]       = make_float2(acc[mi][ni][0], acc[mi][ni][1]);
            *(float2*)&stg[(r + 8) * 328 + c] = make_float2(acc[mi][ni][2], acc[mi][ni][3]);
        }
    __syncthreads();
    for (int i = tid; i < 128 * 75; i += 256) {
        int r = i / 75, c = (i - r * 75) * 4;
        *(float4*)&out[((size_t)hb * 2048 + t0 + r) * 300 + c] = *(float4*)&stg[r * 328 + c];
    }
}

extern "C" void kernel_launch(void* const* d_in, const int* in_sizes, int n_in,
                              void* d_out, int out_size) {
    (void)in_sizes; (void)n_in; (void)out_size;
    const float* in1 = (const float*)d_in[0];
    const float* in2 = (const float*)d_in[1];
    const float* W2  = (const float*)d_in[2];
    const float* b2  = (const float*)d_in[3];
    const float* W3  = (const float*)d_in[4];
    const float* b3  = (const float*)d_in[5];
    float* out = (float*)d_out;

    split_in1<<<(int)((16L * 2048 * KP + 255) / 256), 256>>>(in1);
    split_in2<<<(int)((16L * 512 * KP + 255) / 256), 256>>>(in2);
    wsplit_kernel<<<(2 * 300 * 300 + 255) / 256, 256>>>(W2, W3);
    vt_kernel<<<dim3(16, 10, 16), dim3(32, 8)>>>(in2);

    cudaFuncSetAttribute(proj_mma, cudaFuncAttributeMaxDynamicSharedMemorySize, SMEM_GN2);
    proj_mma<<<dim3(64, 3, 2), 256, SMEM_GN2>>>(b2, b3);

    cudaFuncSetAttribute(scores_kernel, cudaFuncAttributeMaxDynamicSharedMemorySize, SMEM_GN4);
    scores_kernel<<<dim3(16, 2, 32), 256, SMEM_GN4>>>();

    softmax_kernel<<<8192, 256>>>();

    cudaFuncSetAttribute(out_kernel, cudaFuncAttributeMaxDynamicSharedMemorySize, SMEM_OUT);
    out_kernel<<<dim3(16, 1, 32), 256, SMEM_OUT>>>(out);
}